// round 2
// baseline (speedup 1.0000x reference)
#include <cuda_runtime.h>
#include <math.h>

#define S 256
#define B 64
#define D 512
#define T 64
#define V 32000
#define GD 2048  /* 4*D */

// ---------------- scratch (device globals; no runtime allocation) ----------
__device__ float g_xw[(size_t)T * B * GD];   // precomputed x@W_ih^T + b_ih + b_hh, 33.5MB
__device__ float g_hA[B * D];
__device__ float g_hB[B * D];
__device__ float g_c[B * D];
__device__ float g_ctx[B * D];
__device__ float g_hcpre[B * D];
__device__ float g_pe[(size_t)T * B * D];    // all pe vectors, 8.4MB

__device__ __forceinline__ float sigf(float x) { return 1.f / (1.f + expf(-x)); }

// ---------------- init h0 = c0 = feats[S-1] --------------------------------
__global__ void k_init(const float* __restrict__ feats) {
    int i = blockIdx.x * blockDim.x + threadIdx.x;
    float v = feats[(size_t)(S - 1) * B * D + i];
    g_hA[i] = v;
    g_c[i] = v;
}

// ---------------- xW = emb[labels] @ W_ih^T + b_ih + b_hh ------------------
// C[M=T*B=4096][N=2048], K=512. Tile 64x64x16, 256 thr, 4x4 per thread.
__global__ __launch_bounds__(256) void k_xw(const int* __restrict__ labels,
                                            const float* __restrict__ W_ih,
                                            const float* __restrict__ b_ih,
                                            const float* __restrict__ b_hh,
                                            const float* __restrict__ emb) {
    __shared__ float As[64][17];
    __shared__ float Bs[64][17];
    __shared__ int rowlab[64];
    int tid = threadIdx.x;
    int m0 = blockIdx.y * 64;
    int n0 = blockIdx.x * 64;
    if (tid < 64) {
        int m = m0 + tid;
        int t = m / B, b = m % B;
        int lab = labels[b * T + t];
        lab = lab < 0 ? 0 : (lab >= V ? V - 1 : lab);   // defensive clamp
        rowlab[tid] = lab;
    }
    __syncthreads();
    int ty = tid >> 4, tx = tid & 15;
    float acc[4][4] = {};
    for (int k0 = 0; k0 < D; k0 += 16) {
        int row = tid >> 2, seg = tid & 3;
        float4 a = *(const float4*)(emb + (size_t)rowlab[row] * D + k0 + seg * 4);
        As[row][seg * 4 + 0] = a.x; As[row][seg * 4 + 1] = a.y;
        As[row][seg * 4 + 2] = a.z; As[row][seg * 4 + 3] = a.w;
        float4 w = *(const float4*)(W_ih + (size_t)(n0 + row) * D + k0 + seg * 4);
        Bs[row][seg * 4 + 0] = w.x; Bs[row][seg * 4 + 1] = w.y;
        Bs[row][seg * 4 + 2] = w.z; Bs[row][seg * 4 + 3] = w.w;
        __syncthreads();
#pragma unroll
        for (int k = 0; k < 16; k++) {
            float av[4], bv[4];
#pragma unroll
            for (int i = 0; i < 4; i++) av[i] = As[ty * 4 + i][k];
#pragma unroll
            for (int j = 0; j < 4; j++) bv[j] = Bs[tx * 4 + j][k];
#pragma unroll
            for (int i = 0; i < 4; i++)
#pragma unroll
                for (int j = 0; j < 4; j++) acc[i][j] = fmaf(av[i], bv[j], acc[i][j]);
        }
        __syncthreads();
    }
#pragma unroll
    for (int i = 0; i < 4; i++) {
        int m = m0 + ty * 4 + i;
        int n = n0 + tx * 4;
        float* dst = g_xw + (size_t)m * GD + n;
        float4 o;
        o.x = acc[i][0] + b_ih[n + 0] + b_hh[n + 0];
        o.y = acc[i][1] + b_ih[n + 1] + b_hh[n + 1];
        o.z = acc[i][2] + b_ih[n + 2] + b_hh[n + 2];
        o.w = acc[i][3] + b_ih[n + 3] + b_hh[n + 3];
        *(float4*)dst = o;
    }
}

// ---------------- gates = xW[t] + h @ W_hh^T ; fused LSTM cell -------------
// Block handles d in [d0, d0+4) across all 4 gates and all 64 b. Grid 128.
__global__ __launch_bounds__(256) void k_gates(int t, const float* __restrict__ W_hh) {
    const float* h_in = (t & 1) ? g_hB : g_hA;
    float* h_out = (t & 1) ? g_hA : g_hB;
    __shared__ float Asm[64][33];
    __shared__ float Bsm[16][33];
    int tid = threadIdx.x;
    int d0 = blockIdx.x * 4;
    int b = tid & 63, q = tid >> 6;
    float acc0 = 0.f, acc1 = 0.f, acc2 = 0.f, acc3 = 0.f;
    for (int k0 = 0; k0 < D; k0 += 32) {
#pragma unroll
        for (int l = 0; l < 2; l++) {
            int fi = tid * 2 + l;
            int row = fi >> 3, seg = fi & 7;
            float4 v = *(const float4*)(h_in + row * D + k0 + seg * 4);
            Asm[row][seg * 4 + 0] = v.x; Asm[row][seg * 4 + 1] = v.y;
            Asm[row][seg * 4 + 2] = v.z; Asm[row][seg * 4 + 3] = v.w;
        }
        if (tid < 128) {
            int r = tid >> 3, seg = tid & 7;   // r = gi*4 + qq
            int gi = r >> 2, qq = r & 3;
            float4 v = *(const float4*)(W_hh + (size_t)(gi * D + d0 + qq) * D + k0 + seg * 4);
            Bsm[r][seg * 4 + 0] = v.x; Bsm[r][seg * 4 + 1] = v.y;
            Bsm[r][seg * 4 + 2] = v.z; Bsm[r][seg * 4 + 3] = v.w;
        }
        __syncthreads();
#pragma unroll
        for (int k = 0; k < 32; k++) {
            float a = Asm[b][k];
            acc0 = fmaf(a, Bsm[q][k], acc0);
            acc1 = fmaf(a, Bsm[4 + q][k], acc1);
            acc2 = fmaf(a, Bsm[8 + q][k], acc2);
            acc3 = fmaf(a, Bsm[12 + q][k], acc3);
        }
        __syncthreads();
    }
    int d = d0 + q;
    const float* xwrow = g_xw + ((size_t)t * B + b) * GD;
    float ig = acc0 + xwrow[d];
    float fg = acc1 + xwrow[D + d];
    float gg = acc2 + xwrow[2 * D + d];
    float og = acc3 + xwrow[3 * D + d];
    int idx = b * D + d;
    float cn = sigf(fg) * g_c[idx] + sigf(ig) * tanhf(gg);
    g_c[idx] = cn;
    h_out[idx] = sigf(og) * tanhf(cn);
}

// ---------------- attention: scores/softmax/ctx, block per b ---------------
__global__ __launch_bounds__(256) void k_attn(int t, const float* __restrict__ feats) {
    const float* h = (t & 1) ? g_hA : g_hB;  // h_out of this step
    __shared__ float hs[D];
    __shared__ float sc[S];
    __shared__ float tmp[256];
    int b = blockIdx.x, tid = threadIdx.x;
    hs[tid] = h[b * D + tid];
    hs[tid + 256] = h[b * D + tid + 256];
    __syncthreads();
    // score for s = tid
    const float4* f4 = (const float4*)(feats + ((size_t)tid * B + b) * D);
    const float4* h4 = (const float4*)hs;
    float s = 0.f;
#pragma unroll 8
    for (int i = 0; i < D / 4; i++) {
        float4 a = f4[i];
        float4 c = h4[i];
        s += a.x * c.x + a.y * c.y + a.z * c.z + a.w * c.w;
    }
    tmp[tid] = s;
    __syncthreads();
    for (int st = 128; st; st >>= 1) {
        if (tid < st) tmp[tid] = fmaxf(tmp[tid], tmp[tid + st]);
        __syncthreads();
    }
    float mx = tmp[0];
    __syncthreads();
    float e = expf(s - mx);
    tmp[tid] = e;
    __syncthreads();
    for (int st = 128; st; st >>= 1) {
        if (tid < st) tmp[tid] += tmp[tid + st];
        __syncthreads();
    }
    sc[tid] = e / tmp[0];
    __syncthreads();
    // ctx[b, d] = sum_s a[s] * feats[s, b, d]
    float a0 = 0.f, a1 = 0.f;
#pragma unroll 4
    for (int s2 = 0; s2 < S; s2++) {
        const float* fp = feats + ((size_t)s2 * B + b) * D;
        float w = sc[s2];
        a0 = fmaf(w, fp[tid], a0);
        a1 = fmaf(w, fp[tid + 256], a1);
    }
    g_ctx[b * D + tid] = a0;
    g_ctx[b * D + tid + 256] = a1;
}

// ---------------- hcpre = [h, ctx] @ W_hc^T + b_hc -------------------------
// N-tile of 8 per block, grid 64, K=1024 split over h then ctx.
__global__ __launch_bounds__(256) void k_hc(int t, const float* __restrict__ W_hc,
                                            const float* __restrict__ b_hc) {
    const float* h = (t & 1) ? g_hA : g_hB;
    __shared__ float Asm[64][33];
    __shared__ float Bsm[8][33];
    int tid = threadIdx.x;
    int n0 = blockIdx.x * 8;
    int b = tid & 63, q = tid >> 6;
    float acc0 = 0.f, acc1 = 0.f;
    for (int k0 = 0; k0 < 2 * D; k0 += 32) {
        const float* Asrc = (k0 < D) ? h : g_ctx;
        int kk = (k0 < D) ? k0 : (k0 - D);
#pragma unroll
        for (int l = 0; l < 2; l++) {
            int fi = tid * 2 + l;
            int row = fi >> 3, seg = fi & 7;
            float4 v = *(const float4*)(Asrc + row * D + kk + seg * 4);
            Asm[row][seg * 4 + 0] = v.x; Asm[row][seg * 4 + 1] = v.y;
            Asm[row][seg * 4 + 2] = v.z; Asm[row][seg * 4 + 3] = v.w;
        }
        if (tid < 64) {
            int row = tid >> 3, seg = tid & 7;
            float4 v = *(const float4*)(W_hc + (size_t)(n0 + row) * (2 * D) + k0 + seg * 4);
            Bsm[row][seg * 4 + 0] = v.x; Bsm[row][seg * 4 + 1] = v.y;
            Bsm[row][seg * 4 + 2] = v.z; Bsm[row][seg * 4 + 3] = v.w;
        }
        __syncthreads();
#pragma unroll
        for (int k = 0; k < 32; k++) {
            float a = Asm[b][k];
            acc0 = fmaf(a, Bsm[q][k], acc0);
            acc1 = fmaf(a, Bsm[q + 4][k], acc1);
        }
        __syncthreads();
    }
    g_hcpre[b * D + n0 + q] = acc0 + b_hc[n0 + q];
    g_hcpre[b * D + n0 + q + 4] = acc1 + b_hc[n0 + q + 4];
}

// ---------------- LayerNorm + tanh -> pe[t] --------------------------------
__global__ __launch_bounds__(512) void k_ln(int t, const float* __restrict__ ln_g,
                                            const float* __restrict__ ln_b) {
    __shared__ float tmp[512];
    int b = blockIdx.x, tid = threadIdx.x;
    float x = g_hcpre[b * D + tid];
    tmp[tid] = x;
    __syncthreads();
    for (int st = 256; st; st >>= 1) {
        if (tid < st) tmp[tid] += tmp[tid + st];
        __syncthreads();
    }
    float mean = tmp[0] * (1.f / D);
    __syncthreads();
    float dvt = x - mean;
    tmp[tid] = dvt * dvt;
    __syncthreads();
    for (int st = 256; st; st >>= 1) {
        if (tid < st) tmp[tid] += tmp[tid + st];
        __syncthreads();
    }
    float var = tmp[0] * (1.f / D);
    float y = tanhf(fmaf(ln_g[tid], dvt * rsqrtf(var + 1e-5f), ln_b[tid]));
    g_pe[((size_t)t * B + b) * D + tid] = y;
}

// ---------------- logits = PE[4096,512] @ emb[32000,512]^T + bias ----------
__global__ __launch_bounds__(256) void k_logits(const float* __restrict__ emb,
                                                const float* __restrict__ vbias,
                                                float* __restrict__ out) {
    __shared__ float As[64][17];
    __shared__ float Bs[64][17];
    int tid = threadIdx.x;
    int m0 = blockIdx.y * 64;
    int n0 = blockIdx.x * 64;
    int ty = tid >> 4, tx = tid & 15;
    float acc[4][4] = {};
    for (int k0 = 0; k0 < D; k0 += 16) {
        int row = tid >> 2, seg = tid & 3;
        float4 a = *(const float4*)(g_pe + (size_t)(m0 + row) * D + k0 + seg * 4);
        As[row][seg * 4 + 0] = a.x; As[row][seg * 4 + 1] = a.y;
        As[row][seg * 4 + 2] = a.z; As[row][seg * 4 + 3] = a.w;
        float4 w = *(const float4*)(emb + (size_t)(n0 + row) * D + k0 + seg * 4);
        Bs[row][seg * 4 + 0] = w.x; Bs[row][seg * 4 + 1] = w.y;
        Bs[row][seg * 4 + 2] = w.z; Bs[row][seg * 4 + 3] = w.w;
        __syncthreads();
#pragma unroll
        for (int k = 0; k < 16; k++) {
            float av[4], bv[4];
#pragma unroll
            for (int i = 0; i < 4; i++) av[i] = As[ty * 4 + i][k];
#pragma unroll
            for (int j = 0; j < 4; j++) bv[j] = Bs[tx * 4 + j][k];
#pragma unroll
            for (int i = 0; i < 4; i++)
#pragma unroll
                for (int j = 0; j < 4; j++) acc[i][j] = fmaf(av[i], bv[j], acc[i][j]);
        }
        __syncthreads();
    }
    int n = n0 + tx * 4;
    float4 bias = *(const float4*)(vbias + n);
#pragma unroll
    for (int i = 0; i < 4; i++) {
        int m = m0 + ty * 4 + i;   // m = t*B + b  ->  out[t][b][v] = out[m*V + v]
        float4 o;
        o.x = acc[i][0] + bias.x;
        o.y = acc[i][1] + bias.y;
        o.z = acc[i][2] + bias.z;
        o.w = acc[i][3] + bias.w;
        *(float4*)(out + (size_t)m * V + n) = o;
    }
}

// ---------------- launch ----------------------------------------------------
extern "C" void kernel_launch(void* const* d_in, const int* in_sizes, int n_in,
                              void* d_out, int out_size) {
    const float* feats = (const float*)d_in[0];
    const int* labels = (const int*)d_in[1];   // jnp.int64 demotes to int32 under default JAX
    const float* W_ih = (const float*)d_in[2];
    const float* W_hh = (const float*)d_in[3];
    const float* b_ih = (const float*)d_in[4];
    const float* b_hh = (const float*)d_in[5];
    const float* W_hc = (const float*)d_in[6];
    const float* b_hc = (const float*)d_in[7];
    const float* ln_g = (const float*)d_in[8];
    const float* ln_b = (const float*)d_in[9];
    const float* emb = (const float*)d_in[10];
    const float* vbias = (const float*)d_in[11];
    float* out = (float*)d_out;

    k_init<<<(B * D) / 256, 256>>>(feats);
    k_xw<<<dim3(GD / 64, (T * B) / 64), 256>>>(labels, W_ih, b_ih, b_hh, emb);
    for (int t = 0; t < T; t++) {
        k_gates<<<D / 4, 256>>>(t, W_hh);
        k_attn<<<B, 256>>>(t, feats);
        k_hc<<<D / 8, 256>>>(t, W_hc, b_hc);
        k_ln<<<B, 512>>>(t, ln_g, ln_b);
    }
    k_logits<<<dim3(V / 64, (T * B) / 64), 256>>>(emb, vbias, out);
}

// round 3
// speedup vs baseline: 1.3766x; 1.3766x over previous
#include <cuda_runtime.h>
#include <math.h>

#define S 256
#define B 64
#define D 512
#define T 64
#define V 32000
#define GD 2048  /* 4*D */

// ---------------- scratch (device globals; no runtime allocation) ----------
__device__ float g_xw[(size_t)T * B * GD];        // x@W_ih^T + b_ih + b_hh (33.5MB)
__device__ float g_h[(size_t)(T + 1) * B * D];    // h for all steps (slot 0 = h0)
__device__ float g_c[B * D];
__device__ float g_sc[B * S];                     // per-step softmax weights
__device__ float g_ctxall[(size_t)T * B * D];     // ctx for all steps
__device__ float g_hcall[(size_t)T * B * D];      // hc pre-LN for all steps
__device__ float g_pe[(size_t)T * B * D];         // tanh(ln(...)) for all steps

__device__ __forceinline__ float sigf(float x) { return 1.f / (1.f + expf(-x)); }

// ---------------- init h0 = c0 = feats[S-1] --------------------------------
__global__ void k_init(const float* __restrict__ feats) {
    int i = blockIdx.x * blockDim.x + threadIdx.x;
    float v = feats[(size_t)(S - 1) * B * D + i];
    g_h[i] = v;
    g_c[i] = v;
}

// ======================= generic 64x64 FMA-bound tile GEMM =================
// k-major shared tiles: inner loop = 1 broadcast float4 (A) + 1 conflict-free
// float4 (B) per 16 FMA per thread. Register prefetch double-buffers gmem.
template <typename LA, typename LB, typename EP>
__device__ __forceinline__ void gemm_tile(int K, LA loadA, LB loadB, EP epi) {
    __shared__ __align__(16) float As[16][68];   // [k][m]
    __shared__ __align__(16) float Bs[16][68];   // [k][n]
    int tid = threadIdx.x;
    int row = tid >> 2, seg = tid & 3;           // load mapping
    int ty = tid >> 4, tx = tid & 15;            // compute mapping
    float acc[4][4] = {};
    float4 pa = loadA(row, seg * 4);
    float4 pb = loadB(row, seg * 4);
    for (int k0 = 0; k0 < K; k0 += 16) {
        As[seg * 4 + 0][row] = pa.x; As[seg * 4 + 1][row] = pa.y;
        As[seg * 4 + 2][row] = pa.z; As[seg * 4 + 3][row] = pa.w;
        Bs[seg * 4 + 0][row] = pb.x; Bs[seg * 4 + 1][row] = pb.y;
        Bs[seg * 4 + 2][row] = pb.z; Bs[seg * 4 + 3][row] = pb.w;
        __syncthreads();
        if (k0 + 16 < K) {
            pa = loadA(row, k0 + 16 + seg * 4);
            pb = loadB(row, k0 + 16 + seg * 4);
        }
#pragma unroll
        for (int k = 0; k < 16; k++) {
            float4 av = *(const float4*)&As[k][ty * 4];
            float4 bv = *(const float4*)&Bs[k][tx * 4];
            acc[0][0] = fmaf(av.x, bv.x, acc[0][0]); acc[0][1] = fmaf(av.x, bv.y, acc[0][1]);
            acc[0][2] = fmaf(av.x, bv.z, acc[0][2]); acc[0][3] = fmaf(av.x, bv.w, acc[0][3]);
            acc[1][0] = fmaf(av.y, bv.x, acc[1][0]); acc[1][1] = fmaf(av.y, bv.y, acc[1][1]);
            acc[1][2] = fmaf(av.y, bv.z, acc[1][2]); acc[1][3] = fmaf(av.y, bv.w, acc[1][3]);
            acc[2][0] = fmaf(av.z, bv.x, acc[2][0]); acc[2][1] = fmaf(av.z, bv.y, acc[2][1]);
            acc[2][2] = fmaf(av.z, bv.z, acc[2][2]); acc[2][3] = fmaf(av.z, bv.w, acc[2][3]);
            acc[3][0] = fmaf(av.w, bv.x, acc[3][0]); acc[3][1] = fmaf(av.w, bv.y, acc[3][1]);
            acc[3][2] = fmaf(av.w, bv.z, acc[3][2]); acc[3][3] = fmaf(av.w, bv.w, acc[3][3]);
        }
        __syncthreads();
    }
    epi(acc, ty, tx);
}

// ---------------- xW = emb[labels] @ W_ih^T + b_ih + b_hh ------------------
__global__ __launch_bounds__(256) void k_xw(const int* __restrict__ labels,
                                            const float* __restrict__ W_ih,
                                            const float* __restrict__ b_ih,
                                            const float* __restrict__ b_hh,
                                            const float* __restrict__ emb) {
    __shared__ int rowlab[64];
    int tid = threadIdx.x;
    int m0 = blockIdx.y * 64, n0 = blockIdx.x * 64;
    if (tid < 64) {
        int m = m0 + tid;
        int t = m / B, b = m % B;
        int lab = labels[b * T + t];
        lab = lab < 0 ? 0 : (lab >= V ? V - 1 : lab);
        rowlab[tid] = lab;
    }
    __syncthreads();
    auto loadA = [&](int r, int kg) {
        return *(const float4*)(emb + (size_t)rowlab[r] * D + kg);
    };
    auto loadB = [&](int r, int kg) {
        return *(const float4*)(W_ih + (size_t)(n0 + r) * D + kg);
    };
    auto epi = [&](float (&acc)[4][4], int ty, int tx) {
        int n = n0 + tx * 4;
#pragma unroll
        for (int i = 0; i < 4; i++) {
            int m = m0 + ty * 4 + i;
            float4 o;
            o.x = acc[i][0] + b_ih[n + 0] + b_hh[n + 0];
            o.y = acc[i][1] + b_ih[n + 1] + b_hh[n + 1];
            o.z = acc[i][2] + b_ih[n + 2] + b_hh[n + 2];
            o.w = acc[i][3] + b_ih[n + 3] + b_hh[n + 3];
            *(float4*)(g_xw + (size_t)m * GD + n) = o;
        }
    };
    gemm_tile(D, loadA, loadB, epi);
}

// ---------------- gates = xW[t] + h @ W_hh^T ; fused LSTM cell -------------
// Grid 128 (d-tile of 4). Thread (b,q) accumulates gate q for d0..d0+3.
__global__ __launch_bounds__(256) void k_gates(int t, const float* __restrict__ W_hh) {
    const float* h_in = g_h + (size_t)t * B * D;
    float* h_out = g_h + (size_t)(t + 1) * B * D;
    __shared__ __align__(16) float Ah[32][68];   // [k][b]
    __shared__ __align__(16) float Wg[32][16];   // [k][gate*4 + j]
    __shared__ float gsm[4][64][4];
    int tid = threadIdx.x;
    int d0 = blockIdx.x * 4;
    int b = tid & 63, q = tid >> 6;
    // W loader mapping (tid < 128)
    int wr = tid & 15, wks = (tid >> 4) & 7;
    int wq = wr >> 2, wj = wr & 3;
    const float* wptr = W_hh + (size_t)(wq * D + d0 + wj) * D;
    // h loader mapping
    int hb = tid & 63, hks = tid >> 6;
    float4 acc = {0.f, 0.f, 0.f, 0.f};
    float4 ph0 = *(const float4*)(h_in + hb * D + hks * 4);
    float4 ph1 = *(const float4*)(h_in + hb * D + (hks + 4) * 4);
    float4 pw = {0.f, 0.f, 0.f, 0.f};
    if (tid < 128) pw = *(const float4*)(wptr + wks * 4);
    for (int k0 = 0; k0 < D; k0 += 32) {
        Ah[hks * 4 + 0][hb] = ph0.x; Ah[hks * 4 + 1][hb] = ph0.y;
        Ah[hks * 4 + 2][hb] = ph0.z; Ah[hks * 4 + 3][hb] = ph0.w;
        Ah[(hks + 4) * 4 + 0][hb] = ph1.x; Ah[(hks + 4) * 4 + 1][hb] = ph1.y;
        Ah[(hks + 4) * 4 + 2][hb] = ph1.z; Ah[(hks + 4) * 4 + 3][hb] = ph1.w;
        if (tid < 128) {
            Wg[wks * 4 + 0][wr] = pw.x; Wg[wks * 4 + 1][wr] = pw.y;
            Wg[wks * 4 + 2][wr] = pw.z; Wg[wks * 4 + 3][wr] = pw.w;
        }
        __syncthreads();
        if (k0 + 32 < D) {
            ph0 = *(const float4*)(h_in + hb * D + k0 + 32 + hks * 4);
            ph1 = *(const float4*)(h_in + hb * D + k0 + 32 + (hks + 4) * 4);
            if (tid < 128) pw = *(const float4*)(wptr + k0 + 32 + wks * 4);
        }
#pragma unroll
        for (int k = 0; k < 32; k++) {
            float a = Ah[k][b];
            float4 w = *(const float4*)&Wg[k][q * 4];
            acc.x = fmaf(a, w.x, acc.x);
            acc.y = fmaf(a, w.y, acc.y);
            acc.z = fmaf(a, w.z, acc.z);
            acc.w = fmaf(a, w.w, acc.w);
        }
        __syncthreads();
    }
    gsm[q][b][0] = acc.x; gsm[q][b][1] = acc.y;
    gsm[q][b][2] = acc.z; gsm[q][b][3] = acc.w;
    __syncthreads();
    int eb = tid & 63, ej = tid >> 6;
    int d = d0 + ej;
    const float* xwrow = g_xw + ((size_t)t * B + eb) * GD;
    float ig = gsm[0][eb][ej] + xwrow[d];
    float fg = gsm[1][eb][ej] + xwrow[D + d];
    float gg = gsm[2][eb][ej] + xwrow[2 * D + d];
    float og = gsm[3][eb][ej] + xwrow[3 * D + d];
    int idx = eb * D + d;
    float cn = sigf(fg) * g_c[idx] + sigf(ig) * tanhf(gg);
    g_c[idx] = cn;
    h_out[idx] = sigf(og) * tanhf(cn);
}

// ---------------- scores + softmax (grid B, 256 threads = S) ---------------
__global__ __launch_bounds__(256) void k_scores(int t, const float* __restrict__ feats) {
    const float* h = g_h + (size_t)(t + 1) * B * D;
    __shared__ __align__(16) float hs[D];
    __shared__ float red[256];
    int b = blockIdx.x, tid = threadIdx.x;
    hs[tid] = h[b * D + tid];
    hs[tid + 256] = h[b * D + tid + 256];
    __syncthreads();
    const float4* f4 = (const float4*)(feats + ((size_t)tid * B + b) * D);
    const float4* h4 = (const float4*)hs;
    float s = 0.f;
#pragma unroll 8
    for (int i = 0; i < D / 4; i++) {
        float4 a = f4[i], c = h4[i];
        s += a.x * c.x + a.y * c.y + a.z * c.z + a.w * c.w;
    }
    red[tid] = s;
    __syncthreads();
    for (int st = 128; st; st >>= 1) {
        if (tid < st) red[tid] = fmaxf(red[tid], red[tid + st]);
        __syncthreads();
    }
    float mx = red[0];
    __syncthreads();
    float e = expf(s - mx);
    red[tid] = e;
    __syncthreads();
    for (int st = 128; st; st >>= 1) {
        if (tid < st) red[tid] += red[tid + st];
        __syncthreads();
    }
    g_sc[b * S + tid] = e / red[0];
}

// ---------------- ctx (grid (D/64, B), 128 threads) ------------------------
__global__ __launch_bounds__(128) void k_ctx(int t, const float* __restrict__ feats) {
    __shared__ float sc[S];
    __shared__ float psm[64];
    int b = blockIdx.y, d0 = blockIdx.x * 64;
    int tid = threadIdx.x;
    sc[tid] = g_sc[b * S + tid];
    sc[tid + 128] = g_sc[b * S + tid + 128];
    __syncthreads();
    int dl = tid & 63, sh = tid >> 6;
    const float* fp = feats + ((size_t)(sh * 128) * B + b) * D + d0 + dl;
    float acc = 0.f;
#pragma unroll 4
    for (int s2 = 0; s2 < 128; s2++) {
        acc = fmaf(sc[sh * 128 + s2], fp[(size_t)s2 * B * D], acc);
    }
    if (sh == 1) psm[dl] = acc;
    __syncthreads();
    if (sh == 0)
        g_ctxall[((size_t)t * B + b) * D + d0 + dl] = acc + psm[dl];
}

// ---------------- hcall = [h, ctx] @ W_hc^T + b_hc (all steps, one GEMM) ---
__global__ __launch_bounds__(256) void k_hc_all(const float* __restrict__ W_hc,
                                                const float* __restrict__ b_hc) {
    int m0 = blockIdx.y * 64, n0 = blockIdx.x * 64;
    auto loadA = [&](int r, int kg) {
        if (kg < D)
            return *(const float4*)(g_h + (size_t)(m0 + r + B) * D + kg);
        else
            return *(const float4*)(g_ctxall + (size_t)(m0 + r) * D + (kg - D));
    };
    auto loadB = [&](int r, int kg) {
        return *(const float4*)(W_hc + (size_t)(n0 + r) * (2 * D) + kg);
    };
    auto epi = [&](float (&acc)[4][4], int ty, int tx) {
        int n = n0 + tx * 4;
        float4 bias = *(const float4*)(b_hc + n);
#pragma unroll
        for (int i = 0; i < 4; i++) {
            int m = m0 + ty * 4 + i;
            float4 o;
            o.x = acc[i][0] + bias.x; o.y = acc[i][1] + bias.y;
            o.z = acc[i][2] + bias.z; o.w = acc[i][3] + bias.w;
            *(float4*)(g_hcall + (size_t)m * D + n) = o;
        }
    };
    gemm_tile(2 * D, loadA, loadB, epi);
}

// ---------------- batched LayerNorm + tanh -> pe ---------------------------
__global__ __launch_bounds__(128) void k_ln_all(const float* __restrict__ ln_g,
                                                const float* __restrict__ ln_b) {
    int m = blockIdx.x;
    int tid = threadIdx.x;
    __shared__ float wsum[4];
    float4 x = *(const float4*)(g_hcall + (size_t)m * D + tid * 4);
    float s = x.x + x.y + x.z + x.w;
#pragma unroll
    for (int o = 16; o; o >>= 1) s += __shfl_xor_sync(0xffffffff, s, o);
    if ((tid & 31) == 0) wsum[tid >> 5] = s;
    __syncthreads();
    float mean = (wsum[0] + wsum[1] + wsum[2] + wsum[3]) * (1.f / D);
    float4 dv = {x.x - mean, x.y - mean, x.z - mean, x.w - mean};
    float v = dv.x * dv.x + dv.y * dv.y + dv.z * dv.z + dv.w * dv.w;
#pragma unroll
    for (int o = 16; o; o >>= 1) v += __shfl_xor_sync(0xffffffff, v, o);
    __syncthreads();
    if ((tid & 31) == 0) wsum[tid >> 5] = v;
    __syncthreads();
    float var = (wsum[0] + wsum[1] + wsum[2] + wsum[3]) * (1.f / D);
    float rs = rsqrtf(var + 1e-5f);
    float4 gl = *(const float4*)(ln_g + tid * 4);
    float4 bl = *(const float4*)(ln_b + tid * 4);
    float4 y;
    y.x = tanhf(fmaf(gl.x, dv.x * rs, bl.x));
    y.y = tanhf(fmaf(gl.y, dv.y * rs, bl.y));
    y.z = tanhf(fmaf(gl.z, dv.z * rs, bl.z));
    y.w = tanhf(fmaf(gl.w, dv.w * rs, bl.w));
    *(float4*)(g_pe + (size_t)m * D + tid * 4) = y;
}

// ---------------- logits = PE[4096,512] @ emb^T + bias ---------------------
__global__ __launch_bounds__(256) void k_logits(const float* __restrict__ emb,
                                                const float* __restrict__ vbias,
                                                float* __restrict__ out) {
    int m0 = blockIdx.y * 64, n0 = blockIdx.x * 64;
    auto loadA = [&](int r, int kg) {
        return *(const float4*)(g_pe + (size_t)(m0 + r) * D + kg);
    };
    auto loadB = [&](int r, int kg) {
        return *(const float4*)(emb + (size_t)(n0 + r) * D + kg);
    };
    auto epi = [&](float (&acc)[4][4], int ty, int tx) {
        int n = n0 + tx * 4;
        float4 bias = *(const float4*)(vbias + n);
#pragma unroll
        for (int i = 0; i < 4; i++) {
            int m = m0 + ty * 4 + i;
            float4 o;
            o.x = acc[i][0] + bias.x; o.y = acc[i][1] + bias.y;
            o.z = acc[i][2] + bias.z; o.w = acc[i][3] + bias.w;
            *(float4*)(out + (size_t)m * V + n) = o;
        }
    };
    gemm_tile(D, loadA, loadB, epi);
}

// ---------------- launch ----------------------------------------------------
extern "C" void kernel_launch(void* const* d_in, const int* in_sizes, int n_in,
                              void* d_out, int out_size) {
    const float* feats = (const float*)d_in[0];
    const int* labels = (const int*)d_in[1];
    const float* W_ih = (const float*)d_in[2];
    const float* W_hh = (const float*)d_in[3];
    const float* b_ih = (const float*)d_in[4];
    const float* b_hh = (const float*)d_in[5];
    const float* W_hc = (const float*)d_in[6];
    const float* b_hc = (const float*)d_in[7];
    const float* ln_g = (const float*)d_in[8];
    const float* ln_b = (const float*)d_in[9];
    const float* emb = (const float*)d_in[10];
    const float* vbias = (const float*)d_in[11];
    float* out = (float*)d_out;

    k_init<<<(B * D) / 256, 256>>>(feats);
    k_xw<<<dim3(GD / 64, (T * B) / 64), 256>>>(labels, W_ih, b_ih, b_hh, emb);
    for (int t = 0; t < T; t++) {
        k_gates<<<D / 4, 256>>>(t, W_hh);
        k_scores<<<B, 256>>>(t, feats);
        k_ctx<<<dim3(D / 64, B), 128>>>(t, feats);
    }
    k_hc_all<<<dim3(D / 64, (T * B) / 64), 256>>>(W_hc, b_hc);
    k_ln_all<<<T * B, 128>>>(ln_g, ln_b);
    k_logits<<<dim3(V / 64, (T * B) / 64), 256>>>(emb, vbias, out);
}

// round 6
// speedup vs baseline: 2.8309x; 2.0565x over previous
#include <cuda_runtime.h>
#include <cuda_fp16.h>
#include <math.h>
#include <cstdint>

#define S 256
#define B 64
#define D 512
#define T 64
#define V 32000
#define GD 2048  /* 4*D */

// ---------------- scratch (device globals; no runtime allocation) ----------
__device__ float g_xw[(size_t)T * B * GD];        // x@W_ih^T + b_ih + b_hh
__device__ float g_h[(size_t)(T + 1) * B * D];    // h for all steps (slot 0 = h0)
__device__ float g_c[B * D];
__device__ float g_scraw[B * S];                  // raw per-step scores
__device__ float g_ctxall[(size_t)T * B * D];
__device__ float g_hcall[(size_t)T * B * D];
__device__ float g_pe[(size_t)T * B * D];
__device__ __half g_peh[(size_t)T * B * D];
__device__ __half g_pel[(size_t)T * B * D];
__device__ __half g_embh[(size_t)V * D];
__device__ __half g_embl[(size_t)V * D];

__device__ __forceinline__ float sigf(float x) { return 1.f / (1.f + expf(-x)); }

// ======================= PTX helpers ========================================
__device__ __forceinline__ uint32_t smem_u32(const void* p) {
    uint32_t a;
    asm("{ .reg .u64 t; cvta.to.shared.u64 t, %1; cvt.u32.u64 %0, t; }" : "=r"(a) : "l"(p));
    return a;
}
__device__ __forceinline__ uint32_t sw128(uint32_t off) { return off ^ ((off >> 3) & 0x70); }

#define CP_ASYNC16(dst, src) \
    asm volatile("cp.async.cg.shared.global [%0], [%1], 16;" :: "r"(dst), "l"(src) : "memory")
#define CP_COMMIT() asm volatile("cp.async.commit_group;" ::: "memory")
#define CP_WAIT(n) asm volatile("cp.async.wait_group %0;" :: "n"(n) : "memory")

__device__ __forceinline__ void ldsm_x4(uint32_t* r, uint32_t addr) {
    asm volatile("ldmatrix.sync.aligned.m8n8.x4.shared.b16 {%0,%1,%2,%3}, [%4];"
                 : "=r"(r[0]), "=r"(r[1]), "=r"(r[2]), "=r"(r[3]) : "r"(addr));
}
__device__ __forceinline__ void mma16816(float* c, const uint32_t* a, uint32_t b0, uint32_t b1) {
    asm volatile(
        "mma.sync.aligned.m16n8k16.row.col.f32.f16.f16.f32 "
        "{%0,%1,%2,%3}, {%4,%5,%6,%7}, {%8,%9}, {%0,%1,%2,%3};"
        : "+f"(c[0]), "+f"(c[1]), "+f"(c[2]), "+f"(c[3])
        : "r"(a[0]), "r"(a[1]), "r"(a[2]), "r"(a[3]), "r"(b0), "r"(b1));
}

// ---------------- init h0 = c0 = feats[S-1] --------------------------------
__global__ void k_init(const float* __restrict__ feats) {
    int i = blockIdx.x * blockDim.x + threadIdx.x;
    float v = feats[(size_t)(S - 1) * B * D + i];
    g_h[i] = v;
    g_c[i] = v;
}

// ---------------- fp32 -> fp16 hi/lo converter -----------------------------
__global__ void k_cvt(const float* __restrict__ src, __half* __restrict__ dh,
                      __half* __restrict__ dl) {
    int i = blockIdx.x * blockDim.x + threadIdx.x;
    float4 x = ((const float4*)src)[i];
    __half h0 = __float2half_rn(x.x), h1 = __float2half_rn(x.y);
    __half h2 = __float2half_rn(x.z), h3 = __float2half_rn(x.w);
    __half2 ph0 = {h0, h1}, ph1 = {h2, h3};
    __half2 pl0 = {__float2half_rn(x.x - __half2float(h0)),
                   __float2half_rn(x.y - __half2float(h1))};
    __half2 pl1 = {__float2half_rn(x.z - __half2float(h2)),
                   __float2half_rn(x.w - __half2float(h3))};
    ((__half2*)dh)[2 * i] = ph0;
    ((__half2*)dh)[2 * i + 1] = ph1;
    ((__half2*)dl)[2 * i] = pl0;
    ((__half2*)dl)[2 * i + 1] = pl1;
}

// ======================= generic 64x64 FMA tile GEMM (fp32) =================
template <typename LA, typename LB, typename EP>
__device__ __forceinline__ void gemm_tile(int K, LA loadA, LB loadB, EP epi) {
    __shared__ __align__(16) float As[16][68];
    __shared__ __align__(16) float Bs[16][68];
    int tid = threadIdx.x;
    int row = tid >> 2, seg = tid & 3;
    int ty = tid >> 4, tx = tid & 15;
    float acc[4][4] = {};
    float4 pa = loadA(row, seg * 4);
    float4 pb = loadB(row, seg * 4);
    for (int k0 = 0; k0 < K; k0 += 16) {
        As[seg * 4 + 0][row] = pa.x; As[seg * 4 + 1][row] = pa.y;
        As[seg * 4 + 2][row] = pa.z; As[seg * 4 + 3][row] = pa.w;
        Bs[seg * 4 + 0][row] = pb.x; Bs[seg * 4 + 1][row] = pb.y;
        Bs[seg * 4 + 2][row] = pb.z; Bs[seg * 4 + 3][row] = pb.w;
        __syncthreads();
        if (k0 + 16 < K) {
            pa = loadA(row, k0 + 16 + seg * 4);
            pb = loadB(row, k0 + 16 + seg * 4);
        }
#pragma unroll
        for (int k = 0; k < 16; k++) {
            float4 av = *(const float4*)&As[k][ty * 4];
            float4 bv = *(const float4*)&Bs[k][tx * 4];
            acc[0][0] = fmaf(av.x, bv.x, acc[0][0]); acc[0][1] = fmaf(av.x, bv.y, acc[0][1]);
            acc[0][2] = fmaf(av.x, bv.z, acc[0][2]); acc[0][3] = fmaf(av.x, bv.w, acc[0][3]);
            acc[1][0] = fmaf(av.y, bv.x, acc[1][0]); acc[1][1] = fmaf(av.y, bv.y, acc[1][1]);
            acc[1][2] = fmaf(av.y, bv.z, acc[1][2]); acc[1][3] = fmaf(av.y, bv.w, acc[1][3]);
            acc[2][0] = fmaf(av.z, bv.x, acc[2][0]); acc[2][1] = fmaf(av.z, bv.y, acc[2][1]);
            acc[2][2] = fmaf(av.z, bv.z, acc[2][2]); acc[2][3] = fmaf(av.z, bv.w, acc[2][3]);
            acc[3][0] = fmaf(av.w, bv.x, acc[3][0]); acc[3][1] = fmaf(av.w, bv.y, acc[3][1]);
            acc[3][2] = fmaf(av.w, bv.z, acc[3][2]); acc[3][3] = fmaf(av.w, bv.w, acc[3][3]);
        }
        __syncthreads();
    }
    epi(acc, ty, tx);
}

// ---------------- xW = emb[labels] @ W_ih^T + b_ih + b_hh ------------------
__global__ __launch_bounds__(256) void k_xw(const int* __restrict__ labels,
                                            const float* __restrict__ W_ih,
                                            const float* __restrict__ b_ih,
                                            const float* __restrict__ b_hh,
                                            const float* __restrict__ emb) {
    __shared__ int rowlab[64];
    int tid = threadIdx.x;
    int m0 = blockIdx.y * 64, n0 = blockIdx.x * 64;
    if (tid < 64) {
        int m = m0 + tid;
        int t = m / B, b = m % B;
        int lab = labels[b * T + t];
        lab = lab < 0 ? 0 : (lab >= V ? V - 1 : lab);
        rowlab[tid] = lab;
    }
    __syncthreads();
    auto loadA = [&](int r, int kg) {
        return *(const float4*)(emb + (size_t)rowlab[r] * D + kg);
    };
    auto loadB = [&](int r, int kg) {
        return *(const float4*)(W_ih + (size_t)(n0 + r) * D + kg);
    };
    auto epi = [&](float (&acc)[4][4], int ty, int tx) {
        int n = n0 + tx * 4;
#pragma unroll
        for (int i = 0; i < 4; i++) {
            int m = m0 + ty * 4 + i;
            float4 o;
            o.x = acc[i][0] + b_ih[n + 0] + b_hh[n + 0];
            o.y = acc[i][1] + b_ih[n + 1] + b_hh[n + 1];
            o.z = acc[i][2] + b_ih[n + 2] + b_hh[n + 2];
            o.w = acc[i][3] + b_ih[n + 3] + b_hh[n + 3];
            *(float4*)(g_xw + (size_t)m * GD + n) = o;
        }
    };
    gemm_tile(D, loadA, loadB, epi);
}

// ---------------- gates = xW[t] + h @ W_hh^T ; fused LSTM cell -------------
__global__ __launch_bounds__(256) void k_gates(int t, const float* __restrict__ W_hh) {
    const float* h_in = g_h + (size_t)t * B * D;
    float* h_out = g_h + (size_t)(t + 1) * B * D;
    __shared__ __align__(16) float Ah[32][68];
    __shared__ __align__(16) float Wg[32][16];
    __shared__ float gsm[4][64][4];
    int tid = threadIdx.x;
    int d0 = blockIdx.x * 4;
    int b = tid & 63, q = tid >> 6;
    int wr = tid & 15, wks = (tid >> 4) & 7;
    int wq = wr >> 2, wj = wr & 3;
    const float* wptr = W_hh + (size_t)(wq * D + d0 + wj) * D;
    int hb = tid & 63, hks = tid >> 6;
    float4 acc = {0.f, 0.f, 0.f, 0.f};
    float4 ph0 = *(const float4*)(h_in + hb * D + hks * 4);
    float4 ph1 = *(const float4*)(h_in + hb * D + (hks + 4) * 4);
    float4 pw = {0.f, 0.f, 0.f, 0.f};
    if (tid < 128) pw = *(const float4*)(wptr + wks * 4);
    for (int k0 = 0; k0 < D; k0 += 32) {
        Ah[hks * 4 + 0][hb] = ph0.x; Ah[hks * 4 + 1][hb] = ph0.y;
        Ah[hks * 4 + 2][hb] = ph0.z; Ah[hks * 4 + 3][hb] = ph0.w;
        Ah[(hks + 4) * 4 + 0][hb] = ph1.x; Ah[(hks + 4) * 4 + 1][hb] = ph1.y;
        Ah[(hks + 4) * 4 + 2][hb] = ph1.z; Ah[(hks + 4) * 4 + 3][hb] = ph1.w;
        if (tid < 128) {
            Wg[wks * 4 + 0][wr] = pw.x; Wg[wks * 4 + 1][wr] = pw.y;
            Wg[wks * 4 + 2][wr] = pw.z; Wg[wks * 4 + 3][wr] = pw.w;
        }
        __syncthreads();
        if (k0 + 32 < D) {
            ph0 = *(const float4*)(h_in + hb * D + k0 + 32 + hks * 4);
            ph1 = *(const float4*)(h_in + hb * D + k0 + 32 + (hks + 4) * 4);
            if (tid < 128) pw = *(const float4*)(wptr + k0 + 32 + wks * 4);
        }
#pragma unroll
        for (int k = 0; k < 32; k++) {
            float a = Ah[k][b];
            float4 w = *(const float4*)&Wg[k][q * 4];
            acc.x = fmaf(a, w.x, acc.x);
            acc.y = fmaf(a, w.y, acc.y);
            acc.z = fmaf(a, w.z, acc.z);
            acc.w = fmaf(a, w.w, acc.w);
        }
        __syncthreads();
    }
    gsm[q][b][0] = acc.x; gsm[q][b][1] = acc.y;
    gsm[q][b][2] = acc.z; gsm[q][b][3] = acc.w;
    __syncthreads();
    int eb = tid & 63, ej = tid >> 6;
    int d = d0 + ej;
    const float* xwrow = g_xw + ((size_t)t * B + eb) * GD;
    float ig = gsm[0][eb][ej] + xwrow[d];
    float fg = gsm[1][eb][ej] + xwrow[D + d];
    float gg = gsm[2][eb][ej] + xwrow[2 * D + d];
    float og = gsm[3][eb][ej] + xwrow[3 * D + d];
    int idx = eb * D + d;
    float cn = sigf(fg) * g_c[idx] + sigf(ig) * tanhf(gg);
    g_c[idx] = cn;
    h_out[idx] = sigf(og) * tanhf(cn);
}

// ---------------- scores: one warp per (b, s), coalesced over d ------------
__global__ __launch_bounds__(256) void k_scores(int t, const float* __restrict__ feats) {
    const float* h = g_h + (size_t)(t + 1) * B * D;
    int b = blockIdx.y;
    int s = blockIdx.x * 8 + (threadIdx.x >> 5);
    int lane = threadIdx.x & 31;
    const float4* f4 = (const float4*)(feats + ((size_t)s * B + b) * D);
    const float4* h4 = (const float4*)(h + (size_t)b * D);
    float acc = 0.f;
#pragma unroll
    for (int i = 0; i < 4; i++) {
        int idx = i * 32 + lane;
        float4 f = f4[idx], hv = h4[idx];
        acc = fmaf(f.x, hv.x, acc);
        acc = fmaf(f.y, hv.y, acc);
        acc = fmaf(f.z, hv.z, acc);
        acc = fmaf(f.w, hv.w, acc);
    }
#pragma unroll
    for (int o = 16; o; o >>= 1) acc += __shfl_xor_sync(0xffffffff, acc, o);
    if (lane == 0) g_scraw[b * S + s] = acc;
}

// ---------------- ctx with fused softmax (grid (D/64, B), 256 thr) ---------
__global__ __launch_bounds__(256) void k_ctx(int t, const float* __restrict__ feats) {
    __shared__ float w[S];
    __shared__ float red[256];
    __shared__ float psm[4][64];
    int b = blockIdx.y, d0 = blockIdx.x * 64;
    int tid = threadIdx.x;
    float sv = g_scraw[b * S + tid];
    red[tid] = sv;
    __syncthreads();
    for (int st = 128; st; st >>= 1) {
        if (tid < st) red[tid] = fmaxf(red[tid], red[tid + st]);
        __syncthreads();
    }
    float mx = red[0];
    __syncthreads();
    float e = expf(sv - mx);
    red[tid] = e;
    __syncthreads();
    for (int st = 128; st; st >>= 1) {
        if (tid < st) red[tid] += red[tid + st];
        __syncthreads();
    }
    w[tid] = e / red[0];
    __syncthreads();
    int dl = tid & 63, sh = tid >> 6;
    const float* fp = feats + ((size_t)(sh * 64) * B + b) * D + d0 + dl;
    float acc = 0.f;
#pragma unroll 8
    for (int s2 = 0; s2 < 64; s2++)
        acc = fmaf(w[sh * 64 + s2], fp[(size_t)s2 * B * D], acc);
    psm[sh][dl] = acc;
    __syncthreads();
    if (sh == 0)
        g_ctxall[((size_t)t * B + b) * D + d0 + dl] =
            psm[0][dl] + psm[1][dl] + psm[2][dl] + psm[3][dl];
}

// ---------------- hcall = [h, ctx] @ W_hc^T + b_hc -------------------------
__global__ __launch_bounds__(256) void k_hc_all(const float* __restrict__ W_hc,
                                                const float* __restrict__ b_hc) {
    int m0 = blockIdx.y * 64, n0 = blockIdx.x * 64;
    auto loadA = [&](int r, int kg) {
        if (kg < D)
            return *(const float4*)(g_h + (size_t)(m0 + r + B) * D + kg);
        else
            return *(const float4*)(g_ctxall + (size_t)(m0 + r) * D + (kg - D));
    };
    auto loadB = [&](int r, int kg) {
        return *(const float4*)(W_hc + (size_t)(n0 + r) * (2 * D) + kg);
    };
    auto epi = [&](float (&acc)[4][4], int ty, int tx) {
        int n = n0 + tx * 4;
        float4 bias = *(const float4*)(b_hc + n);
#pragma unroll
        for (int i = 0; i < 4; i++) {
            int m = m0 + ty * 4 + i;
            float4 o;
            o.x = acc[i][0] + bias.x; o.y = acc[i][1] + bias.y;
            o.z = acc[i][2] + bias.z; o.w = acc[i][3] + bias.w;
            *(float4*)(g_hcall + (size_t)m * D + n) = o;
        }
    };
    gemm_tile(2 * D, loadA, loadB, epi);
}

// ---------------- batched LayerNorm + tanh -> pe ---------------------------
__global__ __launch_bounds__(128) void k_ln_all(const float* __restrict__ ln_g,
                                                const float* __restrict__ ln_b) {
    int m = blockIdx.x;
    int tid = threadIdx.x;
    __shared__ float wsum[4];
    float4 x = *(const float4*)(g_hcall + (size_t)m * D + tid * 4);
    float s = x.x + x.y + x.z + x.w;
#pragma unroll
    for (int o = 16; o; o >>= 1) s += __shfl_xor_sync(0xffffffff, s, o);
    if ((tid & 31) == 0) wsum[tid >> 5] = s;
    __syncthreads();
    float mean = (wsum[0] + wsum[1] + wsum[2] + wsum[3]) * (1.f / D);
    float4 dv = {x.x - mean, x.y - mean, x.z - mean, x.w - mean};
    float v = dv.x * dv.x + dv.y * dv.y + dv.z * dv.z + dv.w * dv.w;
#pragma unroll
    for (int o = 16; o; o >>= 1) v += __shfl_xor_sync(0xffffffff, v, o);
    __syncthreads();
    if ((tid & 31) == 0) wsum[tid >> 5] = v;
    __syncthreads();
    float var = (wsum[0] + wsum[1] + wsum[2] + wsum[3]) * (1.f / D);
    float rs = rsqrtf(var + 1e-5f);
    float4 gl = *(const float4*)(ln_g + tid * 4);
    float4 bl = *(const float4*)(ln_b + tid * 4);
    float4 y;
    y.x = tanhf(fmaf(gl.x, dv.x * rs, bl.x));
    y.y = tanhf(fmaf(gl.y, dv.y * rs, bl.y));
    y.z = tanhf(fmaf(gl.z, dv.z * rs, bl.z));
    y.w = tanhf(fmaf(gl.w, dv.w * rs, bl.w));
    *(float4*)(g_pe + (size_t)m * D + tid * 4) = y;
}

// ============ logits via mma.sync fp16 hi/lo split ==========================
// C[4096, 32000] = PE @ EMB^T + bias. CTA tile 128x128, K-chunks of 64.
// NT gemm: both operands k-contiguous -> non-trans ldmatrix for A AND B.
#define LG_KC 64
#define LG_COMP_BYTES (128 * 128)
#define LG_STAGE_BYTES (4 * LG_COMP_BYTES)
#define LG_SMEM_REQ (2 * LG_STAGE_BYTES + 1024)

__global__ __launch_bounds__(256) void k_logits_mma(const float* __restrict__ vbias,
                                                    float* __restrict__ out) {
    extern __shared__ char smraw[];
    uint32_t sb = (smem_u32(smraw) + 1023u) & ~1023u;
    int tid = threadIdx.x, warp = tid >> 5, lane = tid & 31;
    int n0 = blockIdx.x * 128, m0 = blockIdx.y * 128;
    int wm = warp & 3, wn = warp >> 2;

    const __half* srcs[4] = {g_peh + (size_t)m0 * D, g_pel + (size_t)m0 * D,
                             g_embh + (size_t)n0 * D, g_embl + (size_t)n0 * D};

    auto issue = [&](int c, int stage) {
        uint32_t sbase = sb + stage * LG_STAGE_BYTES;
#pragma unroll
        for (int i = 0; i < 16; i++) {
            int slot = i * 256 + tid;               // 0..4095
            int comp = slot >> 10, w = slot & 1023;
            int r = w >> 3, ch = w & 7;
            const __half* src = srcs[comp] + (size_t)r * D + c * LG_KC + ch * 8;
            uint32_t dst = sbase + comp * LG_COMP_BYTES + sw128(r * 128 + ch * 16);
            CP_ASYNC16(dst, src);
        }
        CP_COMMIT();
    };

    float acc[2][8][4] = {};
    issue(0, 0);
    for (int c = 0; c < D / LG_KC; c++) {
        if (c + 1 < D / LG_KC) {
            issue(c + 1, (c + 1) & 1);
            CP_WAIT(1);
        } else {
            CP_WAIT(0);
        }
        __syncthreads();
        uint32_t st = sb + (c & 1) * LG_STAGE_BYTES;
        uint32_t Ah_b = st, Al_b = st + LG_COMP_BYTES;
        uint32_t Bh_b = st + 2 * LG_COMP_BYTES, Bl_b = st + 3 * LG_COMP_BYTES;
        // common ldmatrix address pattern for 16-row x 16-half-col block:
        // lanes 0-7: rows 0-7 k0-7 | 8-15: rows 8-15 k0-7 | 16-23: rows 0-7 k8-15 | 24-31: rows 8-15 k8-15
        int lrow = lane & 15;
        uint32_t lcol = (uint32_t)((lane >> 4) << 4);
#pragma unroll
        for (int ks = 0; ks < 4; ks++) {
            uint32_t ah[2][4], al[2][4];
#pragma unroll
            for (int mt = 0; mt < 2; mt++) {
                int r = wm * 32 + mt * 16 + lrow;
                uint32_t bo = sw128((uint32_t)(r * 128 + ks * 32) + lcol);
                ldsm_x4(ah[mt], Ah_b + bo);
                ldsm_x4(al[mt], Al_b + bo);
            }
            // B: non-trans; regs per p: {b0(nt=2p), b0(nt=2p+1), b1(nt=2p), b1(nt=2p+1)}
            uint32_t bh[4][4], bl[4][4];
#pragma unroll
            for (int p = 0; p < 4; p++) {
                int r = wn * 64 + p * 16 + lrow;
                uint32_t bo = sw128((uint32_t)(r * 128 + ks * 32) + lcol);
                ldsm_x4(bh[p], Bh_b + bo);
                ldsm_x4(bl[p], Bl_b + bo);
            }
#pragma unroll
            for (int mt = 0; mt < 2; mt++)
#pragma unroll
                for (int p = 0; p < 4; p++) {
#pragma unroll
                    for (int q = 0; q < 2; q++) {
                        int nt = p * 2 + q;
                        mma16816(acc[mt][nt], ah[mt], bh[p][q], bh[p][q + 2]);
                        mma16816(acc[mt][nt], ah[mt], bl[p][q], bl[p][q + 2]);
                        mma16816(acc[mt][nt], al[mt], bh[p][q], bh[p][q + 2]);
                    }
                }
        }
        __syncthreads();
    }
    // epilogue: c0,c1 -> row lane/4 ; c2,c3 -> row lane/4+8 ; cols (lane%4)*2
#pragma unroll
    for (int mt = 0; mt < 2; mt++) {
        int mrow = m0 + wm * 32 + mt * 16 + (lane >> 2);
#pragma unroll
        for (int nt = 0; nt < 8; nt++) {
            int n = n0 + wn * 64 + nt * 8 + (lane & 3) * 2;
            float2 bv = *(const float2*)(vbias + n);
            float2 o0 = {acc[mt][nt][0] + bv.x, acc[mt][nt][1] + bv.y};
            float2 o1 = {acc[mt][nt][2] + bv.x, acc[mt][nt][3] + bv.y};
            *(float2*)(out + (size_t)mrow * V + n) = o0;
            *(float2*)(out + (size_t)(mrow + 8) * V + n) = o1;
        }
    }
}

// ---------------- launch ----------------------------------------------------
extern "C" void kernel_launch(void* const* d_in, const int* in_sizes, int n_in,
                              void* d_out, int out_size) {
    const float* feats = (const float*)d_in[0];
    const int* labels = (const int*)d_in[1];
    const float* W_ih = (const float*)d_in[2];
    const float* W_hh = (const float*)d_in[3];
    const float* b_ih = (const float*)d_in[4];
    const float* b_hh = (const float*)d_in[5];
    const float* W_hc = (const float*)d_in[6];
    const float* b_hc = (const float*)d_in[7];
    const float* ln_g = (const float*)d_in[8];
    const float* ln_b = (const float*)d_in[9];
    const float* emb = (const float*)d_in[10];
    const float* vbias = (const float*)d_in[11];
    float* out = (float*)d_out;

    cudaFuncSetAttribute(k_logits_mma, cudaFuncAttributeMaxDynamicSharedMemorySize,
                         LG_SMEM_REQ);

    __half *embh, *embl, *peh, *pel;
    float* pe;
    cudaGetSymbolAddress((void**)&embh, g_embh);
    cudaGetSymbolAddress((void**)&embl, g_embl);
    cudaGetSymbolAddress((void**)&peh, g_peh);
    cudaGetSymbolAddress((void**)&pel, g_pel);
    cudaGetSymbolAddress((void**)&pe, g_pe);

    k_init<<<(B * D) / 256, 256>>>(feats);
    k_cvt<<<(V * D / 4) / 256, 256>>>(emb, embh, embl);
    k_xw<<<dim3(GD / 64, (T * B) / 64), 256>>>(labels, W_ih, b_ih, b_hh, emb);
    for (int t = 0; t < T; t++) {
        k_gates<<<D / 4, 256>>>(t, W_hh);
        k_scores<<<dim3(S / 8, B), 256>>>(t, feats);
        k_ctx<<<dim3(D / 64, B), 256>>>(t, feats);
    }
    k_hc_all<<<dim3(D / 64, (T * B) / 64), 256>>>(W_hc, b_hc);
    k_ln_all<<<T * B, 128>>>(ln_g, ln_b);
    k_cvt<<<((size_t)T * B * D / 4) / 256, 256>>>(pe, peh, pel);
    k_logits_mma<<<dim3(V / 128, (T * B) / 128), 256, LG_SMEM_REQ>>>(vbias, out);
}

// round 7
// speedup vs baseline: 2.8862x; 1.0195x over previous
#include <cuda_runtime.h>
#include <cuda_fp16.h>
#include <math.h>
#include <cstdint>

#define S 256
#define B 64
#define D 512
#define T 64
#define V 32000
#define GD 2048  /* 4*D */

// ---------------- scratch (device globals; no runtime allocation) ----------
__device__ float g_xw[(size_t)T * B * GD];        // x@W_ih^T + b_ih + b_hh
__device__ float g_h[(size_t)(T + 1) * B * D];    // h for all steps (slot 0 = h0)
__device__ float g_c[B * D];
__device__ float g_gpart[4 * B * GD];             // k-split partial gate sums
__device__ float g_scraw[B * S];                  // raw per-step scores
__device__ float g_ctxall[(size_t)T * B * D];
__device__ float g_hcall[(size_t)T * B * D];
__device__ __half g_peh[(size_t)T * B * D];
__device__ __half g_pel[(size_t)T * B * D];
__device__ __half g_embh[(size_t)V * D];
__device__ __half g_embl[(size_t)V * D];

__device__ __forceinline__ float sigf(float x) { return 1.f / (1.f + expf(-x)); }

// ======================= PTX helpers ========================================
__device__ __forceinline__ uint32_t smem_u32(const void* p) {
    uint32_t a;
    asm("{ .reg .u64 t; cvta.to.shared.u64 t, %1; cvt.u32.u64 %0, t; }" : "=r"(a) : "l"(p));
    return a;
}
__device__ __forceinline__ uint32_t sw128(uint32_t off) { return off ^ ((off >> 3) & 0x70); }

#define CP_ASYNC16(dst, src) \
    asm volatile("cp.async.cg.shared.global [%0], [%1], 16;" :: "r"(dst), "l"(src) : "memory")
#define CP_COMMIT() asm volatile("cp.async.commit_group;" ::: "memory")
#define CP_WAIT(n) asm volatile("cp.async.wait_group %0;" :: "n"(n) : "memory")

__device__ __forceinline__ void ldsm_x4(uint32_t* r, uint32_t addr) {
    asm volatile("ldmatrix.sync.aligned.m8n8.x4.shared.b16 {%0,%1,%2,%3}, [%4];"
                 : "=r"(r[0]), "=r"(r[1]), "=r"(r[2]), "=r"(r[3]) : "r"(addr));
}
__device__ __forceinline__ void mma16816(float* c, const uint32_t* a, uint32_t b0, uint32_t b1) {
    asm volatile(
        "mma.sync.aligned.m16n8k16.row.col.f32.f16.f16.f32 "
        "{%0,%1,%2,%3}, {%4,%5,%6,%7}, {%8,%9}, {%0,%1,%2,%3};"
        : "+f"(c[0]), "+f"(c[1]), "+f"(c[2]), "+f"(c[3])
        : "r"(a[0]), "r"(a[1]), "r"(a[2]), "r"(a[3]), "r"(b0), "r"(b1));
}

// ---------------- init h0 = c0 = feats[S-1] --------------------------------
__global__ void k_init(const float* __restrict__ feats) {
    int i = blockIdx.x * blockDim.x + threadIdx.x;
    float v = feats[(size_t)(S - 1) * B * D + i];
    g_h[i] = v;
    g_c[i] = v;
}

// ---------------- fp32 -> fp16 hi/lo converter ------------------------------
__global__ void k_cvt(const float* __restrict__ src, __half* __restrict__ dh,
                      __half* __restrict__ dl) {
    int i = blockIdx.x * blockDim.x + threadIdx.x;
    float4 x = ((const float4*)src)[i];
    __half h0 = __float2half_rn(x.x), h1 = __float2half_rn(x.y);
    __half h2 = __float2half_rn(x.z), h3 = __float2half_rn(x.w);
    __half2 ph0 = {h0, h1}, ph1 = {h2, h3};
    __half2 pl0 = {__float2half_rn(x.x - __half2float(h0)),
                   __float2half_rn(x.y - __half2float(h1))};
    __half2 pl1 = {__float2half_rn(x.z - __half2float(h2)),
                   __float2half_rn(x.w - __half2float(h3))};
    ((__half2*)dh)[2 * i] = ph0;
    ((__half2*)dh)[2 * i + 1] = ph1;
    ((__half2*)dl)[2 * i] = pl0;
    ((__half2*)dl)[2 * i + 1] = pl1;
}

// ======================= generic 64x64 FMA tile GEMM (fp32) =================
template <typename LA, typename LB, typename EP>
__device__ __forceinline__ void gemm_tile(int K, LA loadA, LB loadB, EP epi) {
    __shared__ __align__(16) float As[16][68];
    __shared__ __align__(16) float Bs[16][68];
    int tid = threadIdx.x;
    int row = tid >> 2, seg = tid & 3;
    int ty = tid >> 4, tx = tid & 15;
    float acc[4][4] = {};
    float4 pa = loadA(row, seg * 4);
    float4 pb = loadB(row, seg * 4);
    for (int k0 = 0; k0 < K; k0 += 16) {
        As[seg * 4 + 0][row] = pa.x; As[seg * 4 + 1][row] = pa.y;
        As[seg * 4 + 2][row] = pa.z; As[seg * 4 + 3][row] = pa.w;
        Bs[seg * 4 + 0][row] = pb.x; Bs[seg * 4 + 1][row] = pb.y;
        Bs[seg * 4 + 2][row] = pb.z; Bs[seg * 4 + 3][row] = pb.w;
        __syncthreads();
        if (k0 + 16 < K) {
            pa = loadA(row, k0 + 16 + seg * 4);
            pb = loadB(row, k0 + 16 + seg * 4);
        }
#pragma unroll
        for (int k = 0; k < 16; k++) {
            float4 av = *(const float4*)&As[k][ty * 4];
            float4 bv = *(const float4*)&Bs[k][tx * 4];
            acc[0][0] = fmaf(av.x, bv.x, acc[0][0]); acc[0][1] = fmaf(av.x, bv.y, acc[0][1]);
            acc[0][2] = fmaf(av.x, bv.z, acc[0][2]); acc[0][3] = fmaf(av.x, bv.w, acc[0][3]);
            acc[1][0] = fmaf(av.y, bv.x, acc[1][0]); acc[1][1] = fmaf(av.y, bv.y, acc[1][1]);
            acc[1][2] = fmaf(av.y, bv.z, acc[1][2]); acc[1][3] = fmaf(av.y, bv.w, acc[1][3]);
            acc[2][0] = fmaf(av.z, bv.x, acc[2][0]); acc[2][1] = fmaf(av.z, bv.y, acc[2][1]);
            acc[2][2] = fmaf(av.z, bv.z, acc[2][2]); acc[2][3] = fmaf(av.z, bv.w, acc[2][3]);
            acc[3][0] = fmaf(av.w, bv.x, acc[3][0]); acc[3][1] = fmaf(av.w, bv.y, acc[3][1]);
            acc[3][2] = fmaf(av.w, bv.z, acc[3][2]); acc[3][3] = fmaf(av.w, bv.w, acc[3][3]);
        }
        __syncthreads();
    }
    epi(acc, ty, tx);
}

// ---------------- xW = emb[labels] @ W_ih^T + b_ih + b_hh ------------------
__global__ __launch_bounds__(256) void k_xw(const int* __restrict__ labels,
                                            const float* __restrict__ W_ih,
                                            const float* __restrict__ b_ih,
                                            const float* __restrict__ b_hh,
                                            const float* __restrict__ emb) {
    __shared__ int rowlab[64];
    int tid = threadIdx.x;
    int m0 = blockIdx.y * 64, n0 = blockIdx.x * 64;
    if (tid < 64) {
        int m = m0 + tid;
        int t = m / B, b = m % B;
        int lab = labels[b * T + t];
        lab = lab < 0 ? 0 : (lab >= V ? V - 1 : lab);
        rowlab[tid] = lab;
    }
    __syncthreads();
    auto loadA = [&](int r, int kg) {
        return *(const float4*)(emb + (size_t)rowlab[r] * D + kg);
    };
    auto loadB = [&](int r, int kg) {
        return *(const float4*)(W_ih + (size_t)(n0 + r) * D + kg);
    };
    auto epi = [&](float (&acc)[4][4], int ty, int tx) {
        int n = n0 + tx * 4;
#pragma unroll
        for (int i = 0; i < 4; i++) {
            int m = m0 + ty * 4 + i;
            float4 o;
            o.x = acc[i][0] + b_ih[n + 0] + b_hh[n + 0];
            o.y = acc[i][1] + b_ih[n + 1] + b_hh[n + 1];
            o.z = acc[i][2] + b_ih[n + 2] + b_hh[n + 2];
            o.w = acc[i][3] + b_ih[n + 3] + b_hh[n + 3];
            *(float4*)(g_xw + (size_t)m * GD + n) = o;
        }
    };
    gemm_tile(D, loadA, loadB, epi);
}

// ---------------- gates partials: k-split h @ W_hh^T ------------------------
// grid (128 d-tiles, 4 k-splits), 256 thr. Single 128-k smem tile, one sync.
__global__ __launch_bounds__(256) void k_gates(int t, const float* __restrict__ W_hh) {
    const float* h_in = g_h + (size_t)t * B * D;
    __shared__ __align__(16) float4 Ah4[32][64];   // [kq][b] : h[b][kbase+4kq..+3]
    __shared__ __align__(16) float4 Wg4[32][16];   // [kq][r] : r = gate*4 + dj
    int tid = threadIdx.x;
    int d0 = blockIdx.x * 4;
    int kbase = blockIdx.y * 128;
    int b = tid & 63, q = tid >> 6;
    {
        int hb = tid & 63, sl = tid >> 6;
#pragma unroll
        for (int i = 0; i < 8; i++) {
            int kq = sl * 8 + i;
            Ah4[kq][hb] = *(const float4*)(h_in + hb * D + kbase + kq * 4);
        }
        int wr = tid & 15;
        int wq = wr >> 2, wj = wr & 3;
        const float* wrow = W_hh + (size_t)(wq * D + d0 + wj) * D + kbase;
#pragma unroll
        for (int i = 0; i < 2; i++) {
            int kq = (tid >> 4) * 2 + i;
            Wg4[kq][wr] = *(const float4*)(wrow + kq * 4);
        }
    }
    __syncthreads();
    float4 acc = {0.f, 0.f, 0.f, 0.f};
#pragma unroll
    for (int kq = 0; kq < 32; kq++) {
        float4 av = Ah4[kq][b];
        float4 w0 = Wg4[kq][q * 4 + 0];
        float4 w1 = Wg4[kq][q * 4 + 1];
        float4 w2 = Wg4[kq][q * 4 + 2];
        float4 w3 = Wg4[kq][q * 4 + 3];
        acc.x = fmaf(av.x, w0.x, fmaf(av.y, w0.y, fmaf(av.z, w0.z, fmaf(av.w, w0.w, acc.x))));
        acc.y = fmaf(av.x, w1.x, fmaf(av.y, w1.y, fmaf(av.z, w1.z, fmaf(av.w, w1.w, acc.y))));
        acc.z = fmaf(av.x, w2.x, fmaf(av.y, w2.y, fmaf(av.z, w2.z, fmaf(av.w, w2.w, acc.z))));
        acc.w = fmaf(av.x, w3.x, fmaf(av.y, w3.y, fmaf(av.z, w3.z, fmaf(av.w, w3.w, acc.w))));
    }
    // acc.j = partial gate-q value at d0+j for batch b
    float* dst = g_gpart + ((size_t)blockIdx.y * B + b) * GD + q * D + d0;
    *(float4*)dst = acc;
}

// ---------------- cell: combine partials + xw, elementwise LSTM -------------
__global__ __launch_bounds__(256) void k_cell(int t) {
    int idx = blockIdx.x * 256 + threadIdx.x;   // idx = b*512 + d
    int b = idx >> 9, d = idx & 511;
    const float* xwrow = g_xw + ((size_t)t * B + b) * GD;
    float ig = xwrow[d], fg = xwrow[D + d], gg = xwrow[2 * D + d], og = xwrow[3 * D + d];
#pragma unroll
    for (int ks = 0; ks < 4; ks++) {
        const float* gp = g_gpart + ((size_t)ks * B + b) * GD;
        ig += gp[d];
        fg += gp[D + d];
        gg += gp[2 * D + d];
        og += gp[3 * D + d];
    }
    float cn = sigf(fg) * g_c[idx] + sigf(ig) * tanhf(gg);
    g_c[idx] = cn;
    g_h[(size_t)(t + 1) * B * D + idx] = sigf(og) * tanhf(cn);
}

// ---------------- scores: one warp per (b, s), coalesced over d ------------
__global__ __launch_bounds__(256) void k_scores(int t, const float* __restrict__ feats) {
    const float* h = g_h + (size_t)(t + 1) * B * D;
    int b = blockIdx.y;
    int s = blockIdx.x * 8 + (threadIdx.x >> 5);
    int lane = threadIdx.x & 31;
    const float4* f4 = (const float4*)(feats + ((size_t)s * B + b) * D);
    const float4* h4 = (const float4*)(h + (size_t)b * D);
    float acc = 0.f;
#pragma unroll
    for (int i = 0; i < 4; i++) {
        int idx = i * 32 + lane;
        float4 f = f4[idx], hv = h4[idx];
        acc = fmaf(f.x, hv.x, acc);
        acc = fmaf(f.y, hv.y, acc);
        acc = fmaf(f.z, hv.z, acc);
        acc = fmaf(f.w, hv.w, acc);
    }
#pragma unroll
    for (int o = 16; o; o >>= 1) acc += __shfl_xor_sync(0xffffffff, acc, o);
    if (lane == 0) g_scraw[b * S + s] = acc;
}

// ---------------- ctx with fused softmax (grid (D/64, B), 256 thr) ---------
__global__ __launch_bounds__(256) void k_ctx(int t, const float* __restrict__ feats) {
    __shared__ float w[S];
    __shared__ float red[256];
    __shared__ float psm[4][64];
    int b = blockIdx.y, d0 = blockIdx.x * 64;
    int tid = threadIdx.x;
    float sv = g_scraw[b * S + tid];
    red[tid] = sv;
    __syncthreads();
    for (int st = 128; st; st >>= 1) {
        if (tid < st) red[tid] = fmaxf(red[tid], red[tid + st]);
        __syncthreads();
    }
    float mx = red[0];
    __syncthreads();
    float e = expf(sv - mx);
    red[tid] = e;
    __syncthreads();
    for (int st = 128; st; st >>= 1) {
        if (tid < st) red[tid] += red[tid + st];
        __syncthreads();
    }
    w[tid] = e / red[0];
    __syncthreads();
    int dl = tid & 63, sh = tid >> 6;
    const float* fp = feats + ((size_t)(sh * 64) * B + b) * D + d0 + dl;
    float acc = 0.f;
#pragma unroll 8
    for (int s2 = 0; s2 < 64; s2++)
        acc = fmaf(w[sh * 64 + s2], fp[(size_t)s2 * B * D], acc);
    psm[sh][dl] = acc;
    __syncthreads();
    if (sh == 0)
        g_ctxall[((size_t)t * B + b) * D + d0 + dl] =
            psm[0][dl] + psm[1][dl] + psm[2][dl] + psm[3][dl];
}

// ---------------- hcall = [h, ctx] @ W_hc^T + b_hc -------------------------
__global__ __launch_bounds__(256) void k_hc_all(const float* __restrict__ W_hc,
                                                const float* __restrict__ b_hc) {
    int m0 = blockIdx.y * 64, n0 = blockIdx.x * 64;
    auto loadA = [&](int r, int kg) {
        if (kg < D)
            return *(const float4*)(g_h + (size_t)(m0 + r + B) * D + kg);
        else
            return *(const float4*)(g_ctxall + (size_t)(m0 + r) * D + (kg - D));
    };
    auto loadB = [&](int r, int kg) {
        return *(const float4*)(W_hc + (size_t)(n0 + r) * (2 * D) + kg);
    };
    auto epi = [&](float (&acc)[4][4], int ty, int tx) {
        int n = n0 + tx * 4;
        float4 bias = *(const float4*)(b_hc + n);
#pragma unroll
        for (int i = 0; i < 4; i++) {
            int m = m0 + ty * 4 + i;
            float4 o;
            o.x = acc[i][0] + bias.x; o.y = acc[i][1] + bias.y;
            o.z = acc[i][2] + bias.z; o.w = acc[i][3] + bias.w;
            *(float4*)(g_hcall + (size_t)m * D + n) = o;
        }
    };
    gemm_tile(2 * D, loadA, loadB, epi);
}

// ---------------- LayerNorm + tanh -> pe (fp16 hi/lo, fused) ---------------
__global__ __launch_bounds__(128) void k_ln_all(const float* __restrict__ ln_g,
                                                const float* __restrict__ ln_b) {
    int m = blockIdx.x;
    int tid = threadIdx.x;
    __shared__ float wsum[4];
    float4 x = *(const float4*)(g_hcall + (size_t)m * D + tid * 4);
    float s = x.x + x.y + x.z + x.w;
#pragma unroll
    for (int o = 16; o; o >>= 1) s += __shfl_xor_sync(0xffffffff, s, o);
    if ((tid & 31) == 0) wsum[tid >> 5] = s;
    __syncthreads();
    float mean = (wsum[0] + wsum[1] + wsum[2] + wsum[3]) * (1.f / D);
    float4 dv = {x.x - mean, x.y - mean, x.z - mean, x.w - mean};
    float v = dv.x * dv.x + dv.y * dv.y + dv.z * dv.z + dv.w * dv.w;
#pragma unroll
    for (int o = 16; o; o >>= 1) v += __shfl_xor_sync(0xffffffff, v, o);
    __syncthreads();
    if ((tid & 31) == 0) wsum[tid >> 5] = v;
    __syncthreads();
    float var = (wsum[0] + wsum[1] + wsum[2] + wsum[3]) * (1.f / D);
    float rs = rsqrtf(var + 1e-5f);
    float4 gl = *(const float4*)(ln_g + tid * 4);
    float4 bl = *(const float4*)(ln_b + tid * 4);
    float y0 = tanhf(fmaf(gl.x, dv.x * rs, bl.x));
    float y1 = tanhf(fmaf(gl.y, dv.y * rs, bl.y));
    float y2 = tanhf(fmaf(gl.z, dv.z * rs, bl.z));
    float y3 = tanhf(fmaf(gl.w, dv.w * rs, bl.w));
    __half h0 = __float2half_rn(y0), h1 = __float2half_rn(y1);
    __half h2 = __float2half_rn(y2), h3 = __float2half_rn(y3);
    size_t o = (size_t)m * D + tid * 4;
    *(__half2*)&g_peh[o] = {h0, h1};
    *(__half2*)&g_peh[o + 2] = {h2, h3};
    *(__half2*)&g_pel[o] = {__float2half_rn(y0 - __half2float(h0)),
                            __float2half_rn(y1 - __half2float(h1))};
    *(__half2*)&g_pel[o + 2] = {__float2half_rn(y2 - __half2float(h2)),
                                __float2half_rn(y3 - __half2float(h3))};
}

// ============ logits via mma.sync fp16 hi/lo split ==========================
#define LG_KC 64
#define LG_COMP_BYTES (128 * 128)
#define LG_STAGE_BYTES (4 * LG_COMP_BYTES)
#define LG_SMEM_REQ (2 * LG_STAGE_BYTES + 1024)

__global__ __launch_bounds__(256) void k_logits_mma(const float* __restrict__ vbias,
                                                    float* __restrict__ out) {
    extern __shared__ char smraw[];
    uint32_t sb = (smem_u32(smraw) + 1023u) & ~1023u;
    int tid = threadIdx.x, warp = tid >> 5, lane = tid & 31;
    int n0 = blockIdx.x * 128, m0 = blockIdx.y * 128;
    int wm = warp & 3, wn = warp >> 2;

    const __half* srcs[4] = {g_peh + (size_t)m0 * D, g_pel + (size_t)m0 * D,
                             g_embh + (size_t)n0 * D, g_embl + (size_t)n0 * D};

    auto issue = [&](int c, int stage) {
        uint32_t sbase = sb + stage * LG_STAGE_BYTES;
#pragma unroll
        for (int i = 0; i < 16; i++) {
            int slot = i * 256 + tid;
            int comp = slot >> 10, w = slot & 1023;
            int r = w >> 3, ch = w & 7;
            const __half* src = srcs[comp] + (size_t)r * D + c * LG_KC + ch * 8;
            uint32_t dst = sbase + comp * LG_COMP_BYTES + sw128(r * 128 + ch * 16);
            CP_ASYNC16(dst, src);
        }
        CP_COMMIT();
    };

    float acc[2][8][4] = {};
    issue(0, 0);
    for (int c = 0; c < D / LG_KC; c++) {
        if (c + 1 < D / LG_KC) {
            issue(c + 1, (c + 1) & 1);
            CP_WAIT(1);
        } else {
            CP_WAIT(0);
        }
        __syncthreads();
        uint32_t st = sb + (c & 1) * LG_STAGE_BYTES;
        uint32_t Ah_b = st, Al_b = st + LG_COMP_BYTES;
        uint32_t Bh_b = st + 2 * LG_COMP_BYTES, Bl_b = st + 3 * LG_COMP_BYTES;
        int lrow = lane & 15;
        uint32_t lcol = (uint32_t)((lane >> 4) << 4);
#pragma unroll
        for (int ks = 0; ks < 4; ks++) {
            uint32_t ah[2][4], al[2][4];
#pragma unroll
            for (int mt = 0; mt < 2; mt++) {
                int r = wm * 32 + mt * 16 + lrow;
                uint32_t bo = sw128((uint32_t)(r * 128 + ks * 32) + lcol);
                ldsm_x4(ah[mt], Ah_b + bo);
                ldsm_x4(al[mt], Al_b + bo);
            }
            uint32_t bh[4][4], bl[4][4];
#pragma unroll
            for (int p = 0; p < 4; p++) {
                int r = wn * 64 + p * 16 + lrow;
                uint32_t bo = sw128((uint32_t)(r * 128 + ks * 32) + lcol);
                ldsm_x4(bh[p], Bh_b + bo);
                ldsm_x4(bl[p], Bl_b + bo);
            }
#pragma unroll
            for (int mt = 0; mt < 2; mt++)
#pragma unroll
                for (int p = 0; p < 4; p++) {
#pragma unroll
                    for (int q = 0; q < 2; q++) {
                        int nt = p * 2 + q;
                        mma16816(acc[mt][nt], ah[mt], bh[p][q], bh[p][q + 2]);
                        mma16816(acc[mt][nt], ah[mt], bl[p][q], bl[p][q + 2]);
                        mma16816(acc[mt][nt], al[mt], bh[p][q], bh[p][q + 2]);
                    }
                }
        }
        __syncthreads();
    }
#pragma unroll
    for (int mt = 0; mt < 2; mt++) {
        int mrow = m0 + wm * 32 + mt * 16 + (lane >> 2);
#pragma unroll
        for (int nt = 0; nt < 8; nt++) {
            int n = n0 + wn * 64 + nt * 8 + (lane & 3) * 2;
            float2 bv = *(const float2*)(vbias + n);
            float2 o0 = {acc[mt][nt][0] + bv.x, acc[mt][nt][1] + bv.y};
            float2 o1 = {acc[mt][nt][2] + bv.x, acc[mt][nt][3] + bv.y};
            *(float2*)(out + (size_t)mrow * V + n) = o0;
            *(float2*)(out + (size_t)(mrow + 8) * V + n) = o1;
        }
    }
}

// ---------------- launch ----------------------------------------------------
extern "C" void kernel_launch(void* const* d_in, const int* in_sizes, int n_in,
                              void* d_out, int out_size) {
    const float* feats = (const float*)d_in[0];
    const int* labels = (const int*)d_in[1];
    const float* W_ih = (const float*)d_in[2];
    const float* W_hh = (const float*)d_in[3];
    const float* b_ih = (const float*)d_in[4];
    const float* b_hh = (const float*)d_in[5];
    const float* W_hc = (const float*)d_in[6];
    const float* b_hc = (const float*)d_in[7];
    const float* ln_g = (const float*)d_in[8];
    const float* ln_b = (const float*)d_in[9];
    const float* emb = (const float*)d_in[10];
    const float* vbias = (const float*)d_in[11];
    float* out = (float*)d_out;

    cudaFuncSetAttribute(k_logits_mma, cudaFuncAttributeMaxDynamicSharedMemorySize,
                         LG_SMEM_REQ);

    __half *embh, *embl;
    cudaGetSymbolAddress((void**)&embh, g_embh);
    cudaGetSymbolAddress((void**)&embl, g_embl);

    k_init<<<(B * D) / 256, 256>>>(feats);
    k_cvt<<<(V * D / 4) / 256, 256>>>(emb, embh, embl);
    k_xw<<<dim3(GD / 64, (T * B) / 64), 256>>>(labels, W_ih, b_ih, b_hh, emb);
    for (int t = 0; t < T; t++) {
        k_gates<<<dim3(D / 4, 4), 256>>>(t, W_hh);
        k_cell<<<(B * D) / 256, 256>>>(t);
        k_scores<<<dim3(S / 8, B), 256>>>(t, feats);
        k_ctx<<<dim3(D / 64, B), 256>>>(t, feats);
    }
    k_hc_all<<<dim3(D / 64, (T * B) / 64), 256>>>(W_hc, b_hc);
    k_ln_all<<<T * B, 128>>>(ln_g, ln_b);
    k_logits_mma<<<dim3(V / 128, (T * B) / 128), 256, LG_SMEM_REQ>>>(vbias, out);
}

// round 8
// speedup vs baseline: 3.6081x; 1.2501x over previous
#include <cuda_runtime.h>
#include <cuda_fp16.h>
#include <math.h>
#include <cstdint>

#define S 256
#define B 64
#define D 512
#define T 64
#define V 32000
#define GD 2048  /* 4*D */

// ---------------- scratch (device globals; no runtime allocation) ----------
__device__ float g_xw[(size_t)T * B * GD];        // x@W_ih^T + b_ih + b_hh
__device__ float g_h[(size_t)(T + 1) * B * D];    // h for all steps (slot 0 = h0)
__device__ float g_c[B * D];
__device__ float g_gpart[8 * B * GD];             // k-split partial gate sums
__device__ float g_scraw[B * S];                  // raw per-step scores
__device__ float g_ctxall[(size_t)T * B * D];
__device__ float g_hcall[(size_t)T * B * D];
__device__ __half g_peh[(size_t)T * B * D];
__device__ __half g_pel[(size_t)T * B * D];
__device__ __half g_embh[(size_t)V * D];
__device__ __half g_embl[(size_t)V * D];
__device__ __half g_whh_h[(size_t)GD * D];
__device__ __half g_whh_l[(size_t)GD * D];
__device__ __half g_hh16[B * D];                  // current h, fp16 hi
__device__ __half g_hl16[B * D];                  // current h, fp16 lo

__device__ __forceinline__ float sigf(float x) { return 1.f / (1.f + expf(-x)); }

// ======================= PTX helpers ========================================
__device__ __forceinline__ uint32_t smem_u32(const void* p) {
    uint32_t a;
    asm("{ .reg .u64 t; cvta.to.shared.u64 t, %1; cvt.u32.u64 %0, t; }" : "=r"(a) : "l"(p));
    return a;
}
__device__ __forceinline__ uint32_t sw128(uint32_t off) { return off ^ ((off >> 3) & 0x70); }

#define CP_ASYNC16(dst, src) \
    asm volatile("cp.async.cg.shared.global [%0], [%1], 16;" :: "r"(dst), "l"(src) : "memory")
#define CP_COMMIT() asm volatile("cp.async.commit_group;" ::: "memory")
#define CP_WAIT(n) asm volatile("cp.async.wait_group %0;" :: "n"(n) : "memory")

__device__ __forceinline__ void ldsm_x4(uint32_t* r, uint32_t addr) {
    asm volatile("ldmatrix.sync.aligned.m8n8.x4.shared.b16 {%0,%1,%2,%3}, [%4];"
                 : "=r"(r[0]), "=r"(r[1]), "=r"(r[2]), "=r"(r[3]) : "r"(addr));
}
__device__ __forceinline__ void mma16816(float* c, const uint32_t* a, uint32_t b0, uint32_t b1) {
    asm volatile(
        "mma.sync.aligned.m16n8k16.row.col.f32.f16.f16.f32 "
        "{%0,%1,%2,%3}, {%4,%5,%6,%7}, {%8,%9}, {%0,%1,%2,%3};"
        : "+f"(c[0]), "+f"(c[1]), "+f"(c[2]), "+f"(c[3])
        : "r"(a[0]), "r"(a[1]), "r"(a[2]), "r"(a[3]), "r"(b0), "r"(b1));
}

// ---------------- init h0 = c0 = feats[S-1] --------------------------------
__global__ void k_init(const float* __restrict__ feats) {
    int i = blockIdx.x * blockDim.x + threadIdx.x;
    float v = feats[(size_t)(S - 1) * B * D + i];
    g_h[i] = v;
    g_c[i] = v;
    __half hh = __float2half_rn(v);
    g_hh16[i] = hh;
    g_hl16[i] = __float2half_rn(v - __half2float(hh));
}

// ---------------- fp32 -> fp16 hi/lo converter ------------------------------
__global__ void k_cvt(const float* __restrict__ src, __half* __restrict__ dh,
                      __half* __restrict__ dl) {
    int i = blockIdx.x * blockDim.x + threadIdx.x;
    float4 x = ((const float4*)src)[i];
    __half h0 = __float2half_rn(x.x), h1 = __float2half_rn(x.y);
    __half h2 = __float2half_rn(x.z), h3 = __float2half_rn(x.w);
    __half2 ph0 = {h0, h1}, ph1 = {h2, h3};
    __half2 pl0 = {__float2half_rn(x.x - __half2float(h0)),
                   __float2half_rn(x.y - __half2float(h1))};
    __half2 pl1 = {__float2half_rn(x.z - __half2float(h2)),
                   __float2half_rn(x.w - __half2float(h3))};
    ((__half2*)dh)[2 * i] = ph0;
    ((__half2*)dh)[2 * i + 1] = ph1;
    ((__half2*)dl)[2 * i] = pl0;
    ((__half2*)dl)[2 * i + 1] = pl1;
}

// ======================= generic 64x64 FMA tile GEMM (fp32) =================
template <typename LA, typename LB, typename EP>
__device__ __forceinline__ void gemm_tile(int K, LA loadA, LB loadB, EP epi) {
    __shared__ __align__(16) float As[16][68];
    __shared__ __align__(16) float Bs[16][68];
    int tid = threadIdx.x;
    int row = tid >> 2, seg = tid & 3;
    int ty = tid >> 4, tx = tid & 15;
    float acc[4][4] = {};
    float4 pa = loadA(row, seg * 4);
    float4 pb = loadB(row, seg * 4);
    for (int k0 = 0; k0 < K; k0 += 16) {
        As[seg * 4 + 0][row] = pa.x; As[seg * 4 + 1][row] = pa.y;
        As[seg * 4 + 2][row] = pa.z; As[seg * 4 + 3][row] = pa.w;
        Bs[seg * 4 + 0][row] = pb.x; Bs[seg * 4 + 1][row] = pb.y;
        Bs[seg * 4 + 2][row] = pb.z; Bs[seg * 4 + 3][row] = pb.w;
        __syncthreads();
        if (k0 + 16 < K) {
            pa = loadA(row, k0 + 16 + seg * 4);
            pb = loadB(row, k0 + 16 + seg * 4);
        }
#pragma unroll
        for (int k = 0; k < 16; k++) {
            float4 av = *(const float4*)&As[k][ty * 4];
            float4 bv = *(const float4*)&Bs[k][tx * 4];
            acc[0][0] = fmaf(av.x, bv.x, acc[0][0]); acc[0][1] = fmaf(av.x, bv.y, acc[0][1]);
            acc[0][2] = fmaf(av.x, bv.z, acc[0][2]); acc[0][3] = fmaf(av.x, bv.w, acc[0][3]);
            acc[1][0] = fmaf(av.y, bv.x, acc[1][0]); acc[1][1] = fmaf(av.y, bv.y, acc[1][1]);
            acc[1][2] = fmaf(av.y, bv.z, acc[1][2]); acc[1][3] = fmaf(av.y, bv.w, acc[1][3]);
            acc[2][0] = fmaf(av.z, bv.x, acc[2][0]); acc[2][1] = fmaf(av.z, bv.y, acc[2][1]);
            acc[2][2] = fmaf(av.z, bv.z, acc[2][2]); acc[2][3] = fmaf(av.z, bv.w, acc[2][3]);
            acc[3][0] = fmaf(av.w, bv.x, acc[3][0]); acc[3][1] = fmaf(av.w, bv.y, acc[3][1]);
            acc[3][2] = fmaf(av.w, bv.z, acc[3][2]); acc[3][3] = fmaf(av.w, bv.w, acc[3][3]);
        }
        __syncthreads();
    }
    epi(acc, ty, tx);
}

// ---------------- xW = emb[labels] @ W_ih^T + b_ih + b_hh ------------------
__global__ __launch_bounds__(256) void k_xw(const int* __restrict__ labels,
                                            const float* __restrict__ W_ih,
                                            const float* __restrict__ b_ih,
                                            const float* __restrict__ b_hh,
                                            const float* __restrict__ emb) {
    __shared__ int rowlab[64];
    int tid = threadIdx.x;
    int m0 = blockIdx.y * 64, n0 = blockIdx.x * 64;
    if (tid < 64) {
        int m = m0 + tid;
        int t = m / B, b = m % B;
        int lab = labels[b * T + t];
        lab = lab < 0 ? 0 : (lab >= V ? V - 1 : lab);
        rowlab[tid] = lab;
    }
    __syncthreads();
    auto loadA = [&](int r, int kg) {
        return *(const float4*)(emb + (size_t)rowlab[r] * D + kg);
    };
    auto loadB = [&](int r, int kg) {
        return *(const float4*)(W_ih + (size_t)(n0 + r) * D + kg);
    };
    auto epi = [&](float (&acc)[4][4], int ty, int tx) {
        int n = n0 + tx * 4;
#pragma unroll
        for (int i = 0; i < 4; i++) {
            int m = m0 + ty * 4 + i;
            float4 o;
            o.x = acc[i][0] + b_ih[n + 0] + b_hh[n + 0];
            o.y = acc[i][1] + b_ih[n + 1] + b_hh[n + 1];
            o.z = acc[i][2] + b_ih[n + 2] + b_hh[n + 2];
            o.w = acc[i][3] + b_ih[n + 3] + b_hh[n + 3];
            *(float4*)(g_xw + (size_t)m * GD + n) = o;
        }
    };
    gemm_tile(D, loadA, loadB, epi);
}

// ---------------- gates partials via mma: C[b, gatedim] k-split -------------
// grid (GD/64 n-tiles, D/64 k-splits) = (32, 8); 256 thr (8 warps: 2m x 4n).
#define GT_COMP_BYTES (64 * 128)   /* 64 rows x 64 halfs */
__global__ __launch_bounds__(256) void k_gates_mma(int t) {
    __shared__ __align__(1024) char sm[4 * GT_COMP_BYTES];
    uint32_t sb = smem_u32(sm);
    int tid = threadIdx.x, warp = tid >> 5, lane = tid & 31;
    int n0 = blockIdx.x * 64;       // gate-dim tile
    int kb = blockIdx.y * 64;       // k slice
    int wm = warp & 1, wn = warp >> 1;
    const __half* srcs[4] = {g_hh16, g_hl16,
                             g_whh_h + (size_t)n0 * D, g_whh_l + (size_t)n0 * D};
#pragma unroll
    for (int i = 0; i < 8; i++) {
        int slot = i * 256 + tid;        // 0..2047
        int comp = slot >> 9, w = slot & 511;
        int r = w >> 3, ch = w & 7;
        const __half* src = srcs[comp] + (size_t)r * D + kb + ch * 8;
        uint32_t dst = sb + comp * GT_COMP_BYTES + sw128(r * 128 + ch * 16);
        CP_ASYNC16(dst, src);
    }
    CP_COMMIT();
    CP_WAIT(0);
    __syncthreads();
    uint32_t Ah_b = sb, Al_b = sb + GT_COMP_BYTES;
    uint32_t Bh_b = sb + 2 * GT_COMP_BYTES, Bl_b = sb + 3 * GT_COMP_BYTES;
    int lrow = lane & 15;
    uint32_t lcol = (uint32_t)((lane >> 4) << 4);
    float acc[2][2][4] = {};
#pragma unroll
    for (int ks = 0; ks < 4; ks++) {
        uint32_t ah[2][4], al[2][4];
#pragma unroll
        for (int mt = 0; mt < 2; mt++) {
            int r = wm * 32 + mt * 16 + lrow;
            uint32_t bo = sw128((uint32_t)(r * 128 + ks * 32) + lcol);
            ldsm_x4(ah[mt], Ah_b + bo);
            ldsm_x4(al[mt], Al_b + bo);
        }
        uint32_t bh[4], bl[4];
        {
            int r = wn * 16 + lrow;
            uint32_t bo = sw128((uint32_t)(r * 128 + ks * 32) + lcol);
            ldsm_x4(bh, Bh_b + bo);
            ldsm_x4(bl, Bl_b + bo);
        }
#pragma unroll
        for (int mt = 0; mt < 2; mt++)
#pragma unroll
            for (int q = 0; q < 2; q++) {
                mma16816(acc[mt][q], ah[mt], bh[q], bh[q + 2]);
                mma16816(acc[mt][q], ah[mt], bl[q], bl[q + 2]);
                mma16816(acc[mt][q], al[mt], bh[q], bh[q + 2]);
            }
    }
    float* base = g_gpart + (size_t)blockIdx.y * B * GD;
#pragma unroll
    for (int mt = 0; mt < 2; mt++) {
        int br = wm * 32 + mt * 16 + (lane >> 2);
#pragma unroll
        for (int q = 0; q < 2; q++) {
            int n = n0 + wn * 16 + q * 8 + (lane & 3) * 2;
            float2 o0 = {acc[mt][q][0], acc[mt][q][1]};
            float2 o1 = {acc[mt][q][2], acc[mt][q][3]};
            *(float2*)(base + (size_t)br * GD + n) = o0;
            *(float2*)(base + (size_t)(br + 8) * GD + n) = o1;
        }
    }
}

// ---------------- cell: combine partials + xw, elementwise LSTM -------------
__global__ __launch_bounds__(256) void k_cell(int t) {
    int idx = blockIdx.x * 256 + threadIdx.x;   // idx = b*512 + d
    int b = idx >> 9, d = idx & 511;
    const float* xwrow = g_xw + ((size_t)t * B + b) * GD;
    float ig = xwrow[d], fg = xwrow[D + d], gg = xwrow[2 * D + d], og = xwrow[3 * D + d];
#pragma unroll
    for (int ks = 0; ks < 8; ks++) {
        const float* gp = g_gpart + ((size_t)ks * B + b) * GD;
        ig += gp[d];
        fg += gp[D + d];
        gg += gp[2 * D + d];
        og += gp[3 * D + d];
    }
    float cn = sigf(fg) * g_c[idx] + sigf(ig) * tanhf(gg);
    g_c[idx] = cn;
    float hv = sigf(og) * tanhf(cn);
    g_h[(size_t)(t + 1) * B * D + idx] = hv;
    __half hh = __float2half_rn(hv);
    g_hh16[idx] = hh;
    g_hl16[idx] = __float2half_rn(hv - __half2float(hh));
}

// ---------------- scores: one warp per (b, s), coalesced over d ------------
__global__ __launch_bounds__(256) void k_scores(int t, const float* __restrict__ feats) {
    const float* h = g_h + (size_t)(t + 1) * B * D;
    int b = blockIdx.y;
    int s = blockIdx.x * 8 + (threadIdx.x >> 5);
    int lane = threadIdx.x & 31;
    const float4* f4 = (const float4*)(feats + ((size_t)s * B + b) * D);
    const float4* h4 = (const float4*)(h + (size_t)b * D);
    float acc = 0.f;
#pragma unroll
    for (int i = 0; i < 4; i++) {
        int idx = i * 32 + lane;
        float4 f = f4[idx], hv = h4[idx];
        acc = fmaf(f.x, hv.x, acc);
        acc = fmaf(f.y, hv.y, acc);
        acc = fmaf(f.z, hv.z, acc);
        acc = fmaf(f.w, hv.w, acc);
    }
#pragma unroll
    for (int o = 16; o; o >>= 1) acc += __shfl_xor_sync(0xffffffff, acc, o);
    if (lane == 0) g_scraw[b * S + s] = acc;
}

// ---------------- ctx with fused softmax (grid (D/64, B), 256 thr) ---------
__global__ __launch_bounds__(256) void k_ctx(int t, const float* __restrict__ feats) {
    __shared__ float w[S];
    __shared__ float red[256];
    __shared__ float psm[4][64];
    int b = blockIdx.y, d0 = blockIdx.x * 64;
    int tid = threadIdx.x;
    float sv = g_scraw[b * S + tid];
    red[tid] = sv;
    __syncthreads();
    for (int st = 128; st; st >>= 1) {
        if (tid < st) red[tid] = fmaxf(red[tid], red[tid + st]);
        __syncthreads();
    }
    float mx = red[0];
    __syncthreads();
    float e = expf(sv - mx);
    red[tid] = e;
    __syncthreads();
    for (int st = 128; st; st >>= 1) {
        if (tid < st) red[tid] += red[tid + st];
        __syncthreads();
    }
    w[tid] = e / red[0];
    __syncthreads();
    int dl = tid & 63, sh = tid >> 6;
    const float* fp = feats + ((size_t)(sh * 64) * B + b) * D + d0 + dl;
    float acc = 0.f;
#pragma unroll 8
    for (int s2 = 0; s2 < 64; s2++)
        acc = fmaf(w[sh * 64 + s2], fp[(size_t)s2 * B * D], acc);
    psm[sh][dl] = acc;
    __syncthreads();
    if (sh == 0)
        g_ctxall[((size_t)t * B + b) * D + d0 + dl] =
            psm[0][dl] + psm[1][dl] + psm[2][dl] + psm[3][dl];
}

// ---------------- hcall = [h, ctx] @ W_hc^T + b_hc -------------------------
__global__ __launch_bounds__(256) void k_hc_all(const float* __restrict__ W_hc,
                                                const float* __restrict__ b_hc) {
    int m0 = blockIdx.y * 64, n0 = blockIdx.x * 64;
    auto loadA = [&](int r, int kg) {
        if (kg < D)
            return *(const float4*)(g_h + (size_t)(m0 + r + B) * D + kg);
        else
            return *(const float4*)(g_ctxall + (size_t)(m0 + r) * D + (kg - D));
    };
    auto loadB = [&](int r, int kg) {
        return *(const float4*)(W_hc + (size_t)(n0 + r) * (2 * D) + kg);
    };
    auto epi = [&](float (&acc)[4][4], int ty, int tx) {
        int n = n0 + tx * 4;
        float4 bias = *(const float4*)(b_hc + n);
#pragma unroll
        for (int i = 0; i < 4; i++) {
            int m = m0 + ty * 4 + i;
            float4 o;
            o.x = acc[i][0] + bias.x; o.y = acc[i][1] + bias.y;
            o.z = acc[i][2] + bias.z; o.w = acc[i][3] + bias.w;
            *(float4*)(g_hcall + (size_t)m * D + n) = o;
        }
    };
    gemm_tile(2 * D, loadA, loadB, epi);
}

// ---------------- LayerNorm + tanh -> pe (fp16 hi/lo, fused) ---------------
__global__ __launch_bounds__(128) void k_ln_all(const float* __restrict__ ln_g,
                                                const float* __restrict__ ln_b) {
    int m = blockIdx.x;
    int tid = threadIdx.x;
    __shared__ float wsum[4];
    float4 x = *(const float4*)(g_hcall + (size_t)m * D + tid * 4);
    float s = x.x + x.y + x.z + x.w;
#pragma unroll
    for (int o = 16; o; o >>= 1) s += __shfl_xor_sync(0xffffffff, s, o);
    if ((tid & 31) == 0) wsum[tid >> 5] = s;
    __syncthreads();
    float mean = (wsum[0] + wsum[1] + wsum[2] + wsum[3]) * (1.f / D);
    float4 dv = {x.x - mean, x.y - mean, x.z - mean, x.w - mean};
    float v = dv.x * dv.x + dv.y * dv.y + dv.z * dv.z + dv.w * dv.w;
#pragma unroll
    for (int o = 16; o; o >>= 1) v += __shfl_xor_sync(0xffffffff, v, o);
    __syncthreads();
    if ((tid & 31) == 0) wsum[tid >> 5] = v;
    __syncthreads();
    float var = (wsum[0] + wsum[1] + wsum[2] + wsum[3]) * (1.f / D);
    float rs = rsqrtf(var + 1e-5f);
    float4 gl = *(const float4*)(ln_g + tid * 4);
    float4 bl = *(const float4*)(ln_b + tid * 4);
    float y0 = tanhf(fmaf(gl.x, dv.x * rs, bl.x));
    float y1 = tanhf(fmaf(gl.y, dv.y * rs, bl.y));
    float y2 = tanhf(fmaf(gl.z, dv.z * rs, bl.z));
    float y3 = tanhf(fmaf(gl.w, dv.w * rs, bl.w));
    __half h0 = __float2half_rn(y0), h1 = __float2half_rn(y1);
    __half h2 = __float2half_rn(y2), h3 = __float2half_rn(y3);
    size_t o = (size_t)m * D + tid * 4;
    *(__half2*)&g_peh[o] = {h0, h1};
    *(__half2*)&g_peh[o + 2] = {h2, h3};
    *(__half2*)&g_pel[o] = {__float2half_rn(y0 - __half2float(h0)),
                            __float2half_rn(y1 - __half2float(h1))};
    *(__half2*)&g_pel[o + 2] = {__float2half_rn(y2 - __half2float(h2)),
                                __float2half_rn(y3 - __half2float(h3))};
}

// ============ logits via mma.sync fp16 hi/lo split ==========================
#define LG_KC 64
#define LG_COMP_BYTES (128 * 128)
#define LG_STAGE_BYTES (4 * LG_COMP_BYTES)
#define LG_SMEM_REQ (2 * LG_STAGE_BYTES + 1024)

__global__ __launch_bounds__(256) void k_logits_mma(const float* __restrict__ vbias,
                                                    float* __restrict__ out) {
    extern __shared__ char smraw[];
    uint32_t sb = (smem_u32(smraw) + 1023u) & ~1023u;
    int tid = threadIdx.x, warp = tid >> 5, lane = tid & 31;
    int n0 = blockIdx.x * 128, m0 = blockIdx.y * 128;
    int wm = warp & 3, wn = warp >> 2;

    const __half* srcs[4] = {g_peh + (size_t)m0 * D, g_pel + (size_t)m0 * D,
                             g_embh + (size_t)n0 * D, g_embl + (size_t)n0 * D};

    auto issue = [&](int c, int stage) {
        uint32_t sbase = sb + stage * LG_STAGE_BYTES;
#pragma unroll
        for (int i = 0; i < 16; i++) {
            int slot = i * 256 + tid;
            int comp = slot >> 10, w = slot & 1023;
            int r = w >> 3, ch = w & 7;
            const __half* src = srcs[comp] + (size_t)r * D + c * LG_KC + ch * 8;
            uint32_t dst = sbase + comp * LG_COMP_BYTES + sw128(r * 128 + ch * 16);
            CP_ASYNC16(dst, src);
        }
        CP_COMMIT();
    };

    float acc[2][8][4] = {};
    issue(0, 0);
    for (int c = 0; c < D / LG_KC; c++) {
        if (c + 1 < D / LG_KC) {
            issue(c + 1, (c + 1) & 1);
            CP_WAIT(1);
        } else {
            CP_WAIT(0);
        }
        __syncthreads();
        uint32_t st = sb + (c & 1) * LG_STAGE_BYTES;
        uint32_t Ah_b = st, Al_b = st + LG_COMP_BYTES;
        uint32_t Bh_b = st + 2 * LG_COMP_BYTES, Bl_b = st + 3 * LG_COMP_BYTES;
        int lrow = lane & 15;
        uint32_t lcol = (uint32_t)((lane >> 4) << 4);
#pragma unroll
        for (int ks = 0; ks < 4; ks++) {
            uint32_t ah[2][4], al[2][4];
#pragma unroll
            for (int mt = 0; mt < 2; mt++) {
                int r = wm * 32 + mt * 16 + lrow;
                uint32_t bo = sw128((uint32_t)(r * 128 + ks * 32) + lcol);
                ldsm_x4(ah[mt], Ah_b + bo);
                ldsm_x4(al[mt], Al_b + bo);
            }
            uint32_t bh[4][4], bl[4][4];
#pragma unroll
            for (int p = 0; p < 4; p++) {
                int r = wn * 64 + p * 16 + lrow;
                uint32_t bo = sw128((uint32_t)(r * 128 + ks * 32) + lcol);
                ldsm_x4(bh[p], Bh_b + bo);
                ldsm_x4(bl[p], Bl_b + bo);
            }
#pragma unroll
            for (int mt = 0; mt < 2; mt++)
#pragma unroll
                for (int p = 0; p < 4; p++) {
#pragma unroll
                    for (int q = 0; q < 2; q++) {
                        int nt = p * 2 + q;
                        mma16816(acc[mt][nt], ah[mt], bh[p][q], bh[p][q + 2]);
                        mma16816(acc[mt][nt], ah[mt], bl[p][q], bl[p][q + 2]);
                        mma16816(acc[mt][nt], al[mt], bh[p][q], bh[p][q + 2]);
                    }
                }
        }
        __syncthreads();
    }
#pragma unroll
    for (int mt = 0; mt < 2; mt++) {
        int mrow = m0 + wm * 32 + mt * 16 + (lane >> 2);
#pragma unroll
        for (int nt = 0; nt < 8; nt++) {
            int n = n0 + wn * 64 + nt * 8 + (lane & 3) * 2;
            float2 bv = *(const float2*)(vbias + n);
            float2 o0 = {acc[mt][nt][0] + bv.x, acc[mt][nt][1] + bv.y};
            float2 o1 = {acc[mt][nt][2] + bv.x, acc[mt][nt][3] + bv.y};
            *(float2*)(out + (size_t)mrow * V + n) = o0;
            *(float2*)(out + (size_t)(mrow + 8) * V + n) = o1;
        }
    }
}

// ---------------- launch ----------------------------------------------------
extern "C" void kernel_launch(void* const* d_in, const int* in_sizes, int n_in,
                              void* d_out, int out_size) {
    const float* feats = (const float*)d_in[0];
    const int* labels = (const int*)d_in[1];
    const float* W_ih = (const float*)d_in[2];
    const float* W_hh = (const float*)d_in[3];
    const float* b_ih = (const float*)d_in[4];
    const float* b_hh = (const float*)d_in[5];
    const float* W_hc = (const float*)d_in[6];
    const float* b_hc = (const float*)d_in[7];
    const float* ln_g = (const float*)d_in[8];
    const float* ln_b = (const float*)d_in[9];
    const float* emb = (const float*)d_in[10];
    const float* vbias = (const float*)d_in[11];
    float* out = (float*)d_out;

    cudaFuncSetAttribute(k_logits_mma, cudaFuncAttributeMaxDynamicSharedMemorySize,
                         LG_SMEM_REQ);

    __half *embh, *embl, *whhh, *whhl;
    cudaGetSymbolAddress((void**)&embh, g_embh);
    cudaGetSymbolAddress((void**)&embl, g_embl);
    cudaGetSymbolAddress((void**)&whhh, g_whh_h);
    cudaGetSymbolAddress((void**)&whhl, g_whh_l);

    k_init<<<(B * D) / 256, 256>>>(feats);
    k_cvt<<<(V * D / 4) / 256, 256>>>(emb, embh, embl);
    k_cvt<<<(GD * D / 4) / 256, 256>>>(W_hh, whhh, whhl);
    k_xw<<<dim3(GD / 64, (T * B) / 64), 256>>>(labels, W_ih, b_ih, b_hh, emb);
    for (int t = 0; t < T; t++) {
        k_gates_mma<<<dim3(GD / 64, D / 64), 256>>>(t);
        k_cell<<<(B * D) / 256, 256>>>(t);
        k_scores<<<dim3(S / 8, B), 256>>>(t, feats);
        k_ctx<<<dim3(D / 64, B), 256>>>(t, feats);
    }
    k_hc_all<<<dim3(D / 64, (T * B) / 64), 256>>>(W_hc, b_hc);
    k_ln_all<<<T * B, 128>>>(ln_g, ln_b);
    k_logits_mma<<<dim3(V / 128, (T * B) / 128), 256, LG_SMEM_REQ>>>(vbias, out);
}

// round 9
// speedup vs baseline: 3.9935x; 1.1068x over previous
#include <cuda_runtime.h>
#include <cuda_fp16.h>
#include <math.h>
#include <cstdint>

#define S 256
#define B 64
#define D 512
#define T 64
#define V 32000
#define GD 2048  /* 4*D */

// ---------------- scratch (device globals; no runtime allocation) ----------
__device__ float g_xw[(size_t)T * B * GD];        // x@W_ih^T + b_ih + b_hh
__device__ float g_h[(size_t)(T + 1) * B * D];    // h for all steps (slot 0 = h0)
__device__ float g_c[B * D];
__device__ float g_gpart[8 * B * GD];             // k-split partial gate sums
__device__ float g_scraw[B * S];                  // raw per-step scores
__device__ float g_hcall[(size_t)T * B * D];      // hc pre-LN
__device__ __half g_peh[(size_t)T * B * D];
__device__ __half g_pel[(size_t)T * B * D];
__device__ __half g_embh[(size_t)V * D];
__device__ __half g_embl[(size_t)V * D];
__device__ __half g_whh_h[(size_t)GD * D];
__device__ __half g_whh_l[(size_t)GD * D];
__device__ __half g_wih_h[(size_t)GD * D];
__device__ __half g_wih_l[(size_t)GD * D];
__device__ __half g_whc_h[(size_t)D * 2 * D];
__device__ __half g_whc_l[(size_t)D * 2 * D];
__device__ __half g_hh16[B * D];                  // current h, fp16 hi
__device__ __half g_hl16[B * D];                  // current h, fp16 lo
__device__ __half g_hcinh[(size_t)T * B * 2 * D]; // [h|ctx] hi, [4096,1024]
__device__ __half g_hcinl[(size_t)T * B * 2 * D]; // [h|ctx] lo

__device__ __forceinline__ float sigf(float x) { return 1.f / (1.f + expf(-x)); }

// ======================= PTX helpers ========================================
__device__ __forceinline__ uint32_t smem_u32(const void* p) {
    uint32_t a;
    asm("{ .reg .u64 t; cvta.to.shared.u64 t, %1; cvt.u32.u64 %0, t; }" : "=r"(a) : "l"(p));
    return a;
}
__device__ __forceinline__ uint32_t sw128(uint32_t off) { return off ^ ((off >> 3) & 0x70); }

#define CP_ASYNC16(dst, src) \
    asm volatile("cp.async.cg.shared.global [%0], [%1], 16;" :: "r"(dst), "l"(src) : "memory")
#define CP_COMMIT() asm volatile("cp.async.commit_group;" ::: "memory")
#define CP_WAIT(n) asm volatile("cp.async.wait_group %0;" :: "n"(n) : "memory")

__device__ __forceinline__ void ldsm_x4(uint32_t* r, uint32_t addr) {
    asm volatile("ldmatrix.sync.aligned.m8n8.x4.shared.b16 {%0,%1,%2,%3}, [%4];"
                 : "=r"(r[0]), "=r"(r[1]), "=r"(r[2]), "=r"(r[3]) : "r"(addr));
}
__device__ __forceinline__ void mma16816(float* c, const uint32_t* a, uint32_t b0, uint32_t b1) {
    asm volatile(
        "mma.sync.aligned.m16n8k16.row.col.f32.f16.f16.f32 "
        "{%0,%1,%2,%3}, {%4,%5,%6,%7}, {%8,%9}, {%0,%1,%2,%3};"
        : "+f"(c[0]), "+f"(c[1]), "+f"(c[2]), "+f"(c[3])
        : "r"(a[0]), "r"(a[1]), "r"(a[2]), "r"(a[3]), "r"(b0), "r"(b1));
}

// ---------------- init h0 = c0 = feats[S-1] --------------------------------
__global__ void k_init(const float* __restrict__ feats) {
    int i = blockIdx.x * blockDim.x + threadIdx.x;
    float v = feats[(size_t)(S - 1) * B * D + i];
    g_h[i] = v;
    g_c[i] = v;
    __half hh = __float2half_rn(v);
    g_hh16[i] = hh;
    g_hl16[i] = __float2half_rn(v - __half2float(hh));
}

// ---------------- fp32 -> fp16 hi/lo converter ------------------------------
__global__ void k_cvt(const float* __restrict__ src, __half* __restrict__ dh,
                      __half* __restrict__ dl) {
    int i = blockIdx.x * blockDim.x + threadIdx.x;
    float4 x = ((const float4*)src)[i];
    __half h0 = __float2half_rn(x.x), h1 = __float2half_rn(x.y);
    __half h2 = __float2half_rn(x.z), h3 = __float2half_rn(x.w);
    __half2 ph0 = {h0, h1}, ph1 = {h2, h3};
    __half2 pl0 = {__float2half_rn(x.x - __half2float(h0)),
                   __float2half_rn(x.y - __half2float(h1))};
    __half2 pl1 = {__float2half_rn(x.z - __half2float(h2)),
                   __float2half_rn(x.w - __half2float(h3))};
    ((__half2*)dh)[2 * i] = ph0;
    ((__half2*)dh)[2 * i + 1] = ph1;
    ((__half2*)dl)[2 * i] = pl0;
    ((__half2*)dl)[2 * i + 1] = pl1;
}

// ======================= shared mma tile machinery ==========================
#define LG_KC 64
#define LG_COMP_BYTES (128 * 128)
#define LG_STAGE_BYTES (4 * LG_COMP_BYTES)
#define LG_SMEM_REQ (2 * LG_STAGE_BYTES + 1024)

// Core 128x128 3-product hi/lo mma over KCH chunks; frag maps verified in R6.
// acc[2][8][4]; warp tile 32x64 (wm=warp&3, wn=warp>>2).
template <int KCH, typename ISSUE>
__device__ __forceinline__ void mma_tile_128(uint32_t sb, ISSUE issue,
                                             float (&acc)[2][8][4],
                                             int warp, int lane) {
    int wm = warp & 3, wn = warp >> 2;
    issue(0, 0);
    for (int c = 0; c < KCH; c++) {
        if (c + 1 < KCH) {
            issue(c + 1, (c + 1) & 1);
            CP_WAIT(1);
        } else {
            CP_WAIT(0);
        }
        __syncthreads();
        uint32_t st = sb + (c & 1) * LG_STAGE_BYTES;
        uint32_t Ah_b = st, Al_b = st + LG_COMP_BYTES;
        uint32_t Bh_b = st + 2 * LG_COMP_BYTES, Bl_b = st + 3 * LG_COMP_BYTES;
        int lrow = lane & 15;
        uint32_t lcol = (uint32_t)((lane >> 4) << 4);
#pragma unroll
        for (int ks = 0; ks < 4; ks++) {
            uint32_t ah[2][4], al[2][4];
#pragma unroll
            for (int mt = 0; mt < 2; mt++) {
                int r = wm * 32 + mt * 16 + lrow;
                uint32_t bo = sw128((uint32_t)(r * 128 + ks * 32) + lcol);
                ldsm_x4(ah[mt], Ah_b + bo);
                ldsm_x4(al[mt], Al_b + bo);
            }
            uint32_t bh[4][4], bl[4][4];
#pragma unroll
            for (int p = 0; p < 4; p++) {
                int r = wn * 64 + p * 16 + lrow;
                uint32_t bo = sw128((uint32_t)(r * 128 + ks * 32) + lcol);
                ldsm_x4(bh[p], Bh_b + bo);
                ldsm_x4(bl[p], Bl_b + bo);
            }
#pragma unroll
            for (int mt = 0; mt < 2; mt++)
#pragma unroll
                for (int p = 0; p < 4; p++) {
#pragma unroll
                    for (int q = 0; q < 2; q++) {
                        int nt = p * 2 + q;
                        mma16816(acc[mt][nt], ah[mt], bh[p][q], bh[p][q + 2]);
                        mma16816(acc[mt][nt], ah[mt], bl[p][q], bl[p][q + 2]);
                        mma16816(acc[mt][nt], al[mt], bh[p][q], bh[p][q + 2]);
                    }
                }
        }
        __syncthreads();
    }
}

// ---------------- xW = emb[labels] @ W_ih^T + b_ih + b_hh (mma) ------------
__global__ __launch_bounds__(256) void k_xw_mma(const int* __restrict__ labels,
                                                const float* __restrict__ b_ih,
                                                const float* __restrict__ b_hh) {
    extern __shared__ char smraw[];
    __shared__ int rowlab[128];
    uint32_t sb = (smem_u32(smraw) + 1023u) & ~1023u;
    int tid = threadIdx.x, warp = tid >> 5, lane = tid & 31;
    int n0 = blockIdx.x * 128, m0 = blockIdx.y * 128;
    if (tid < 128) {
        int m = m0 + tid;
        int lab = labels[(m & 63) * T + (m >> 6)];
        rowlab[tid] = lab < 0 ? 0 : (lab >= V ? V - 1 : lab);
    }
    __syncthreads();
    auto issue = [&](int c, int stage) {
        uint32_t sbase = sb + stage * LG_STAGE_BYTES;
#pragma unroll
        for (int i = 0; i < 16; i++) {
            int slot = i * 256 + tid;
            int comp = slot >> 10, w = slot & 1023;
            int r = w >> 3, ch = w & 7;
            const __half* src;
            if (comp == 0)      src = g_embh + (size_t)rowlab[r] * D;
            else if (comp == 1) src = g_embl + (size_t)rowlab[r] * D;
            else if (comp == 2) src = g_wih_h + (size_t)(n0 + r) * D;
            else                src = g_wih_l + (size_t)(n0 + r) * D;
            src += c * LG_KC + ch * 8;
            uint32_t dst = sbase + comp * LG_COMP_BYTES + sw128(r * 128 + ch * 16);
            CP_ASYNC16(dst, src);
        }
        CP_COMMIT();
    };
    float acc[2][8][4] = {};
    mma_tile_128<D / LG_KC>(sb, issue, acc, warp, lane);
    int wm = warp & 3, wn = warp >> 2;
#pragma unroll
    for (int mt = 0; mt < 2; mt++) {
        int mrow = m0 + wm * 32 + mt * 16 + (lane >> 2);
#pragma unroll
        for (int nt = 0; nt < 8; nt++) {
            int n = n0 + wn * 64 + nt * 8 + (lane & 3) * 2;
            float2 bi = *(const float2*)(b_ih + n);
            float2 bh2 = *(const float2*)(b_hh + n);
            float2 o0 = {acc[mt][nt][0] + bi.x + bh2.x, acc[mt][nt][1] + bi.y + bh2.y};
            float2 o1 = {acc[mt][nt][2] + bi.x + bh2.x, acc[mt][nt][3] + bi.y + bh2.y};
            *(float2*)(g_xw + (size_t)mrow * GD + n) = o0;
            *(float2*)(g_xw + (size_t)(mrow + 8) * GD + n) = o1;
        }
    }
}

// ---------------- gates partials via mma: C[b, gatedim] k-split -------------
#define GT_COMP_BYTES (64 * 128)
__global__ __launch_bounds__(256) void k_gates_mma(int t) {
    __shared__ __align__(1024) char sm[4 * GT_COMP_BYTES];
    uint32_t sb = smem_u32(sm);
    int tid = threadIdx.x, warp = tid >> 5, lane = tid & 31;
    int n0 = blockIdx.x * 64;
    int kb = blockIdx.y * 64;
    int wm = warp & 1, wn = warp >> 1;
    const __half* srcs[4] = {g_hh16, g_hl16,
                             g_whh_h + (size_t)n0 * D, g_whh_l + (size_t)n0 * D};
#pragma unroll
    for (int i = 0; i < 8; i++) {
        int slot = i * 256 + tid;
        int comp = slot >> 9, w = slot & 511;
        int r = w >> 3, ch = w & 7;
        const __half* src = srcs[comp] + (size_t)r * D + kb + ch * 8;
        uint32_t dst = sb + comp * GT_COMP_BYTES + sw128(r * 128 + ch * 16);
        CP_ASYNC16(dst, src);
    }
    CP_COMMIT();
    CP_WAIT(0);
    __syncthreads();
    uint32_t Ah_b = sb, Al_b = sb + GT_COMP_BYTES;
    uint32_t Bh_b = sb + 2 * GT_COMP_BYTES, Bl_b = sb + 3 * GT_COMP_BYTES;
    int lrow = lane & 15;
    uint32_t lcol = (uint32_t)((lane >> 4) << 4);
    float acc[2][2][4] = {};
#pragma unroll
    for (int ks = 0; ks < 4; ks++) {
        uint32_t ah[2][4], al[2][4];
#pragma unroll
        for (int mt = 0; mt < 2; mt++) {
            int r = wm * 32 + mt * 16 + lrow;
            uint32_t bo = sw128((uint32_t)(r * 128 + ks * 32) + lcol);
            ldsm_x4(ah[mt], Ah_b + bo);
            ldsm_x4(al[mt], Al_b + bo);
        }
        uint32_t bh[4], bl[4];
        {
            int r = wn * 16 + lrow;
            uint32_t bo = sw128((uint32_t)(r * 128 + ks * 32) + lcol);
            ldsm_x4(bh, Bh_b + bo);
            ldsm_x4(bl, Bl_b + bo);
        }
#pragma unroll
        for (int mt = 0; mt < 2; mt++)
#pragma unroll
            for (int q = 0; q < 2; q++) {
                mma16816(acc[mt][q], ah[mt], bh[q], bh[q + 2]);
                mma16816(acc[mt][q], ah[mt], bl[q], bl[q + 2]);
                mma16816(acc[mt][q], al[mt], bh[q], bh[q + 2]);
            }
    }
    float* base = g_gpart + (size_t)blockIdx.y * B * GD;
#pragma unroll
    for (int mt = 0; mt < 2; mt++) {
        int br = wm * 32 + mt * 16 + (lane >> 2);
#pragma unroll
        for (int q = 0; q < 2; q++) {
            int n = n0 + wn * 16 + q * 8 + (lane & 3) * 2;
            float2 o0 = {acc[mt][q][0], acc[mt][q][1]};
            float2 o1 = {acc[mt][q][2], acc[mt][q][3]};
            *(float2*)(base + (size_t)br * GD + n) = o0;
            *(float2*)(base + (size_t)(br + 8) * GD + n) = o1;
        }
    }
}

// ---------------- cell: combine partials + xw, elementwise LSTM -------------
__global__ __launch_bounds__(256) void k_cell(int t) {
    int idx = blockIdx.x * 256 + threadIdx.x;   // idx = b*512 + d
    int b = idx >> 9, d = idx & 511;
    const float* xwrow = g_xw + ((size_t)t * B + b) * GD;
    float ig = xwrow[d], fg = xwrow[D + d], gg = xwrow[2 * D + d], og = xwrow[3 * D + d];
#pragma unroll
    for (int ks = 0; ks < 8; ks++) {
        const float* gp = g_gpart + ((size_t)ks * B + b) * GD;
        ig += gp[d];
        fg += gp[D + d];
        gg += gp[2 * D + d];
        og += gp[3 * D + d];
    }
    float cn = sigf(fg) * g_c[idx] + sigf(ig) * tanhf(gg);
    g_c[idx] = cn;
    float hv = sigf(og) * tanhf(cn);
    g_h[(size_t)(t + 1) * B * D + idx] = hv;
    __half hh = __float2half_rn(hv);
    __half hl = __float2half_rn(hv - __half2float(hh));
    g_hh16[idx] = hh;
    g_hl16[idx] = hl;
    size_t mrow = (size_t)t * B + b;
    g_hcinh[mrow * 2 * D + d] = hh;
    g_hcinl[mrow * 2 * D + d] = hl;
}

// ---------------- scores: one warp per (b, s), coalesced over d ------------
__global__ __launch_bounds__(256) void k_scores(int t, const float* __restrict__ feats) {
    const float* h = g_h + (size_t)(t + 1) * B * D;
    int b = blockIdx.y;
    int s = blockIdx.x * 8 + (threadIdx.x >> 5);
    int lane = threadIdx.x & 31;
    const float4* f4 = (const float4*)(feats + ((size_t)s * B + b) * D);
    const float4* h4 = (const float4*)(h + (size_t)b * D);
    float acc = 0.f;
#pragma unroll
    for (int i = 0; i < 4; i++) {
        int idx = i * 32 + lane;
        float4 f = f4[idx], hv = h4[idx];
        acc = fmaf(f.x, hv.x, acc);
        acc = fmaf(f.y, hv.y, acc);
        acc = fmaf(f.z, hv.z, acc);
        acc = fmaf(f.w, hv.w, acc);
    }
#pragma unroll
    for (int o = 16; o; o >>= 1) acc += __shfl_xor_sync(0xffffffff, acc, o);
    if (lane == 0) g_scraw[b * S + s] = acc;
}

// ---------------- ctx with fused softmax; writes fp16 hi/lo into hcin -------
__global__ __launch_bounds__(256) void k_ctx(int t, const float* __restrict__ feats) {
    __shared__ float w[S];
    __shared__ float red[256];
    __shared__ float psm[4][64];
    int b = blockIdx.y, d0 = blockIdx.x * 64;
    int tid = threadIdx.x;
    float sv = g_scraw[b * S + tid];
    red[tid] = sv;
    __syncthreads();
    for (int st = 128; st; st >>= 1) {
        if (tid < st) red[tid] = fmaxf(red[tid], red[tid + st]);
        __syncthreads();
    }
    float mx = red[0];
    __syncthreads();
    float e = expf(sv - mx);
    red[tid] = e;
    __syncthreads();
    for (int st = 128; st; st >>= 1) {
        if (tid < st) red[tid] += red[tid + st];
        __syncthreads();
    }
    w[tid] = e / red[0];
    __syncthreads();
    int dl = tid & 63, sh = tid >> 6;
    const float* fp = feats + ((size_t)(sh * 64) * B + b) * D + d0 + dl;
    float acc = 0.f;
#pragma unroll 8
    for (int s2 = 0; s2 < 64; s2++)
        acc = fmaf(w[sh * 64 + s2], fp[(size_t)s2 * B * D], acc);
    psm[sh][dl] = acc;
    __syncthreads();
    if (sh == 0) {
        float cv = psm[0][dl] + psm[1][dl] + psm[2][dl] + psm[3][dl];
        __half ch = __float2half_rn(cv);
        size_t mrow = (size_t)t * B + b;
        g_hcinh[mrow * 2 * D + D + d0 + dl] = ch;
        g_hcinl[mrow * 2 * D + D + d0 + dl] = __float2half_rn(cv - __half2float(ch));
    }
}

// ---------------- hcall = [h, ctx] @ W_hc^T + b_hc (mma) --------------------
__global__ __launch_bounds__(256) void k_hc_mma(const float* __restrict__ b_hc) {
    extern __shared__ char smraw[];
    uint32_t sb = (smem_u32(smraw) + 1023u) & ~1023u;
    int tid = threadIdx.x, warp = tid >> 5, lane = tid & 31;
    int n0 = blockIdx.x * 128, m0 = blockIdx.y * 128;
    auto issue = [&](int c, int stage) {
        uint32_t sbase = sb + stage * LG_STAGE_BYTES;
#pragma unroll
        for (int i = 0; i < 16; i++) {
            int slot = i * 256 + tid;
            int comp = slot >> 10, w = slot & 1023;
            int r = w >> 3, ch = w & 7;
            const __half* src;
            if (comp == 0)      src = g_hcinh + (size_t)(m0 + r) * 2 * D;
            else if (comp == 1) src = g_hcinl + (size_t)(m0 + r) * 2 * D;
            else if (comp == 2) src = g_whc_h + (size_t)(n0 + r) * 2 * D;
            else                src = g_whc_l + (size_t)(n0 + r) * 2 * D;
            src += c * LG_KC + ch * 8;
            uint32_t dst = sbase + comp * LG_COMP_BYTES + sw128(r * 128 + ch * 16);
            CP_ASYNC16(dst, src);
        }
        CP_COMMIT();
    };
    float acc[2][8][4] = {};
    mma_tile_128<2 * D / LG_KC>(sb, issue, acc, warp, lane);
    int wm = warp & 3, wn = warp >> 2;
#pragma unroll
    for (int mt = 0; mt < 2; mt++) {
        int mrow = m0 + wm * 32 + mt * 16 + (lane >> 2);
#pragma unroll
        for (int nt = 0; nt < 8; nt++) {
            int n = n0 + wn * 64 + nt * 8 + (lane & 3) * 2;
            float2 bv = *(const float2*)(b_hc + n);
            float2 o0 = {acc[mt][nt][0] + bv.x, acc[mt][nt][1] + bv.y};
            float2 o1 = {acc[mt][nt][2] + bv.x, acc[mt][nt][3] + bv.y};
            *(float2*)(g_hcall + (size_t)mrow * D + n) = o0;
            *(float2*)(g_hcall + (size_t)(mrow + 8) * D + n) = o1;
        }
    }
}

// ---------------- LayerNorm + tanh -> pe (fp16 hi/lo, fused) ---------------
__global__ __launch_bounds__(128) void k_ln_all(const float* __restrict__ ln_g,
                                                const float* __restrict__ ln_b) {
    int m = blockIdx.x;
    int tid = threadIdx.x;
    __shared__ float wsum[4];
    float4 x = *(const float4*)(g_hcall + (size_t)m * D + tid * 4);
    float s = x.x + x.y + x.z + x.w;
#pragma unroll
    for (int o = 16; o; o >>= 1) s += __shfl_xor_sync(0xffffffff, s, o);
    if ((tid & 31) == 0) wsum[tid >> 5] = s;
    __syncthreads();
    float mean = (wsum[0] + wsum[1] + wsum[2] + wsum[3]) * (1.f / D);
    float4 dv = {x.x - mean, x.y - mean, x.z - mean, x.w - mean};
    float v = dv.x * dv.x + dv.y * dv.y + dv.z * dv.z + dv.w * dv.w;
#pragma unroll
    for (int o = 16; o; o >>= 1) v += __shfl_xor_sync(0xffffffff, v, o);
    __syncthreads();
    if ((tid & 31) == 0) wsum[tid >> 5] = v;
    __syncthreads();
    float var = (wsum[0] + wsum[1] + wsum[2] + wsum[3]) * (1.f / D);
    float rs = rsqrtf(var + 1e-5f);
    float4 gl = *(const float4*)(ln_g + tid * 4);
    float4 bl = *(const float4*)(ln_b + tid * 4);
    float y0 = tanhf(fmaf(gl.x, dv.x * rs, bl.x));
    float y1 = tanhf(fmaf(gl.y, dv.y * rs, bl.y));
    float y2 = tanhf(fmaf(gl.z, dv.z * rs, bl.z));
    float y3 = tanhf(fmaf(gl.w, dv.w * rs, bl.w));
    __half h0 = __float2half_rn(y0), h1 = __float2half_rn(y1);
    __half h2 = __float2half_rn(y2), h3 = __float2half_rn(y3);
    size_t o = (size_t)m * D + tid * 4;
    *(__half2*)&g_peh[o] = {h0, h1};
    *(__half2*)&g_peh[o + 2] = {h2, h3};
    *(__half2*)&g_pel[o] = {__float2half_rn(y0 - __half2float(h0)),
                            __float2half_rn(y1 - __half2float(h1))};
    *(__half2*)&g_pel[o + 2] = {__float2half_rn(y2 - __half2float(h2)),
                                __float2half_rn(y3 - __half2float(h3))};
}

// ============ logits via mma.sync fp16 hi/lo split ==========================
__global__ __launch_bounds__(256) void k_logits_mma(const float* __restrict__ vbias,
                                                    float* __restrict__ out) {
    extern __shared__ char smraw[];
    uint32_t sb = (smem_u32(smraw) + 1023u) & ~1023u;
    int tid = threadIdx.x, warp = tid >> 5, lane = tid & 31;
    int n0 = blockIdx.x * 128, m0 = blockIdx.y * 128;
    const __half* srcs[4] = {g_peh + (size_t)m0 * D, g_pel + (size_t)m0 * D,
                             g_embh + (size_t)n0 * D, g_embl + (size_t)n0 * D};
    auto issue = [&](int c, int stage) {
        uint32_t sbase = sb + stage * LG_STAGE_BYTES;
#pragma unroll
        for (int i = 0; i < 16; i++) {
            int slot = i * 256 + tid;
            int comp = slot >> 10, w = slot & 1023;
            int r = w >> 3, ch = w & 7;
            const __half* src = srcs[comp] + (size_t)r * D + c * LG_KC + ch * 8;
            uint32_t dst = sbase + comp * LG_COMP_BYTES + sw128(r * 128 + ch * 16);
            CP_ASYNC16(dst, src);
        }
        CP_COMMIT();
    };
    float acc[2][8][4] = {};
    mma_tile_128<D / LG_KC>(sb, issue, acc, warp, lane);
    int wm = warp & 3, wn = warp >> 2;
#pragma unroll
    for (int mt = 0; mt < 2; mt++) {
        int mrow = m0 + wm * 32 + mt * 16 + (lane >> 2);
#pragma unroll
        for (int nt = 0; nt < 8; nt++) {
            int n = n0 + wn * 64 + nt * 8 + (lane & 3) * 2;
            float2 bv = *(const float2*)(vbias + n);
            float2 o0 = {acc[mt][nt][0] + bv.x, acc[mt][nt][1] + bv.y};
            float2 o1 = {acc[mt][nt][2] + bv.x, acc[mt][nt][3] + bv.y};
            *(float2*)(out + (size_t)mrow * V + n) = o0;
            *(float2*)(out + (size_t)(mrow + 8) * V + n) = o1;
        }
    }
}

// ---------------- launch ----------------------------------------------------
extern "C" void kernel_launch(void* const* d_in, const int* in_sizes, int n_in,
                              void* d_out, int out_size) {
    const float* feats = (const float*)d_in[0];
    const int* labels = (const int*)d_in[1];
    const float* W_ih = (const float*)d_in[2];
    const float* W_hh = (const float*)d_in[3];
    const float* b_ih = (const float*)d_in[4];
    const float* b_hh = (const float*)d_in[5];
    const float* W_hc = (const float*)d_in[6];
    const float* b_hc = (const float*)d_in[7];
    const float* ln_g = (const float*)d_in[8];
    const float* ln_b = (const float*)d_in[9];
    const float* emb = (const float*)d_in[10];
    const float* vbias = (const float*)d_in[11];
    float* out = (float*)d_out;

    cudaFuncSetAttribute(k_logits_mma, cudaFuncAttributeMaxDynamicSharedMemorySize,
                         LG_SMEM_REQ);
    cudaFuncSetAttribute(k_xw_mma, cudaFuncAttributeMaxDynamicSharedMemorySize,
                         LG_SMEM_REQ);
    cudaFuncSetAttribute(k_hc_mma, cudaFuncAttributeMaxDynamicSharedMemorySize,
                         LG_SMEM_REQ);

    __half *embh, *embl, *whhh, *whhl, *wihh, *wihl, *whch, *whcl;
    cudaGetSymbolAddress((void**)&embh, g_embh);
    cudaGetSymbolAddress((void**)&embl, g_embl);
    cudaGetSymbolAddress((void**)&whhh, g_whh_h);
    cudaGetSymbolAddress((void**)&whhl, g_whh_l);
    cudaGetSymbolAddress((void**)&wihh, g_wih_h);
    cudaGetSymbolAddress((void**)&wihl, g_wih_l);
    cudaGetSymbolAddress((void**)&whch, g_whc_h);
    cudaGetSymbolAddress((void**)&whcl, g_whc_l);

    k_init<<<(B * D) / 256, 256>>>(feats);
    k_cvt<<<(V * D / 4) / 256, 256>>>(emb, embh, embl);
    k_cvt<<<(GD * D / 4) / 256, 256>>>(W_hh, whhh, whhl);
    k_cvt<<<(GD * D / 4) / 256, 256>>>(W_ih, wihh, wihl);
    k_cvt<<<(D * 2 * D / 4) / 256, 256>>>(W_hc, whch, whcl);
    k_xw_mma<<<dim3(GD / 128, (T * B) / 128), 256, LG_SMEM_REQ>>>(labels, b_ih, b_hh);
    for (int t = 0; t < T; t++) {
        k_gates_mma<<<dim3(GD / 64, D / 64), 256>>>(t);
        k_cell<<<(B * D) / 256, 256>>>(t);
        k_scores<<<dim3(S / 8, B), 256>>>(t, feats);
        k_ctx<<<dim3(D / 64, B), 256>>>(t, feats);
    }
    k_hc_mma<<<dim3(D / 128, (T * B) / 128), 256, LG_SMEM_REQ>>>(b_hc);
    k_ln_all<<<T * B, 128>>>(ln_g, ln_b);
    k_logits_mma<<<dim3(V / 128, (T * B) / 128), 256, LG_SMEM_REQ>>>(vbias, out);
}

// round 10
// speedup vs baseline: 4.1469x; 1.0384x over previous
#include <cuda_runtime.h>
#include <cuda_fp16.h>
#include <math.h>
#include <cstdint>

#define S 256
#define B 64
#define D 512
#define T 64
#define V 32000
#define GD 2048  /* 4*D */

// ---------------- scratch (device globals; no runtime allocation) ----------
__device__ float g_xw[(size_t)T * B * GD];        // x@W_ih^T + b_ih + b_hh
__device__ float g_c[B * D];
__device__ float g_gpart[8 * B * GD];             // k-split partial gate sums
__device__ float g_hcall[(size_t)T * B * D];      // hc pre-LN
__device__ __half g_peh[(size_t)T * B * D];
__device__ __half g_pel[(size_t)T * B * D];
__device__ __half g_embh[(size_t)V * D];
__device__ __half g_embl[(size_t)V * D];
__device__ __half g_whh_h[(size_t)GD * D];
__device__ __half g_whh_l[(size_t)GD * D];
__device__ __half g_wih_h[(size_t)GD * D];
__device__ __half g_wih_l[(size_t)GD * D];
__device__ __half g_whc_h[(size_t)D * 2 * D];
__device__ __half g_whc_l[(size_t)D * 2 * D];
__device__ __half g_hh16[B * D];                  // current h, fp16 hi
__device__ __half g_hl16[B * D];                  // current h, fp16 lo
__device__ __half g_hcinh[(size_t)T * B * 2 * D]; // [h|ctx] hi, [4096,1024]
__device__ __half g_hcinl[(size_t)T * B * 2 * D]; // [h|ctx] lo

__device__ __forceinline__ float sigf(float x) { return 1.f / (1.f + expf(-x)); }

// ======================= PTX helpers ========================================
__device__ __forceinline__ uint32_t smem_u32(const void* p) {
    uint32_t a;
    asm("{ .reg .u64 t; cvta.to.shared.u64 t, %1; cvt.u32.u64 %0, t; }" : "=r"(a) : "l"(p));
    return a;
}
__device__ __forceinline__ uint32_t sw128(uint32_t off) { return off ^ ((off >> 3) & 0x70); }

#define CP_ASYNC16(dst, src) \
    asm volatile("cp.async.cg.shared.global [%0], [%1], 16;" :: "r"(dst), "l"(src) : "memory")
#define CP_COMMIT() asm volatile("cp.async.commit_group;" ::: "memory")
#define CP_WAIT(n) asm volatile("cp.async.wait_group %0;" :: "n"(n) : "memory")

__device__ __forceinline__ void ldsm_x4(uint32_t* r, uint32_t addr) {
    asm volatile("ldmatrix.sync.aligned.m8n8.x4.shared.b16 {%0,%1,%2,%3}, [%4];"
                 : "=r"(r[0]), "=r"(r[1]), "=r"(r[2]), "=r"(r[3]) : "r"(addr));
}
__device__ __forceinline__ void mma16816(float* c, const uint32_t* a, uint32_t b0, uint32_t b1) {
    asm volatile(
        "mma.sync.aligned.m16n8k16.row.col.f32.f16.f16.f32 "
        "{%0,%1,%2,%3}, {%4,%5,%6,%7}, {%8,%9}, {%0,%1,%2,%3};"
        : "+f"(c[0]), "+f"(c[1]), "+f"(c[2]), "+f"(c[3])
        : "r"(a[0]), "r"(a[1]), "r"(a[2]), "r"(a[3]), "r"(b0), "r"(b1));
}

// ---------------- init h0 = c0 = feats[S-1] --------------------------------
__global__ void k_init(const float* __restrict__ feats) {
    int i = blockIdx.x * blockDim.x + threadIdx.x;
    float v = feats[(size_t)(S - 1) * B * D + i];
    g_c[i] = v;
    __half hh = __float2half_rn(v);
    g_hh16[i] = hh;
    g_hl16[i] = __float2half_rn(v - __half2float(hh));
}

// ---------------- fp32 -> fp16 hi/lo converter ------------------------------
__global__ void k_cvt(const float* __restrict__ src, __half* __restrict__ dh,
                      __half* __restrict__ dl) {
    int i = blockIdx.x * blockDim.x + threadIdx.x;
    float4 x = ((const float4*)src)[i];
    __half h0 = __float2half_rn(x.x), h1 = __float2half_rn(x.y);
    __half h2 = __float2half_rn(x.z), h3 = __float2half_rn(x.w);
    __half2 ph0 = {h0, h1}, ph1 = {h2, h3};
    __half2 pl0 = {__float2half_rn(x.x - __half2float(h0)),
                   __float2half_rn(x.y - __half2float(h1))};
    __half2 pl1 = {__float2half_rn(x.z - __half2float(h2)),
                   __float2half_rn(x.w - __half2float(h3))};
    ((__half2*)dh)[2 * i] = ph0;
    ((__half2*)dh)[2 * i + 1] = ph1;
    ((__half2*)dl)[2 * i] = pl0;
    ((__half2*)dl)[2 * i + 1] = pl1;
}

// ======================= shared mma tile machinery ==========================
#define LG_KC 64
#define LG_COMP_BYTES (128 * 128)
#define LG_STAGE_BYTES (4 * LG_COMP_BYTES)
#define LG_SMEM_REQ (2 * LG_STAGE_BYTES + 1024)

template <int KCH, typename ISSUE>
__device__ __forceinline__ void mma_tile_128(uint32_t sb, ISSUE issue,
                                             float (&acc)[2][8][4],
                                             int warp, int lane) {
    int wm = warp & 3, wn = warp >> 2;
    issue(0, 0);
    for (int c = 0; c < KCH; c++) {
        if (c + 1 < KCH) {
            issue(c + 1, (c + 1) & 1);
            CP_WAIT(1);
        } else {
            CP_WAIT(0);
        }
        __syncthreads();
        uint32_t st = sb + (c & 1) * LG_STAGE_BYTES;
        uint32_t Ah_b = st, Al_b = st + LG_COMP_BYTES;
        uint32_t Bh_b = st + 2 * LG_COMP_BYTES, Bl_b = st + 3 * LG_COMP_BYTES;
        int lrow = lane & 15;
        uint32_t lcol = (uint32_t)((lane >> 4) << 4);
#pragma unroll
        for (int ks = 0; ks < 4; ks++) {
            uint32_t ah[2][4], al[2][4];
#pragma unroll
            for (int mt = 0; mt < 2; mt++) {
                int r = wm * 32 + mt * 16 + lrow;
                uint32_t bo = sw128((uint32_t)(r * 128 + ks * 32) + lcol);
                ldsm_x4(ah[mt], Ah_b + bo);
                ldsm_x4(al[mt], Al_b + bo);
            }
            uint32_t bh[4][4], bl[4][4];
#pragma unroll
            for (int p = 0; p < 4; p++) {
                int r = wn * 64 + p * 16 + lrow;
                uint32_t bo = sw128((uint32_t)(r * 128 + ks * 32) + lcol);
                ldsm_x4(bh[p], Bh_b + bo);
                ldsm_x4(bl[p], Bl_b + bo);
            }
#pragma unroll
            for (int mt = 0; mt < 2; mt++)
#pragma unroll
                for (int p = 0; p < 4; p++) {
#pragma unroll
                    for (int q = 0; q < 2; q++) {
                        int nt = p * 2 + q;
                        mma16816(acc[mt][nt], ah[mt], bh[p][q], bh[p][q + 2]);
                        mma16816(acc[mt][nt], ah[mt], bl[p][q], bl[p][q + 2]);
                        mma16816(acc[mt][nt], al[mt], bh[p][q], bh[p][q + 2]);
                    }
                }
        }
        __syncthreads();
    }
}

// ---------------- xW = emb[labels] @ W_ih^T + b_ih + b_hh (mma) ------------
__global__ __launch_bounds__(256) void k_xw_mma(const int* __restrict__ labels,
                                                const float* __restrict__ b_ih,
                                                const float* __restrict__ b_hh) {
    extern __shared__ char smraw[];
    __shared__ int rowlab[128];
    uint32_t sb = (smem_u32(smraw) + 1023u) & ~1023u;
    int tid = threadIdx.x, warp = tid >> 5, lane = tid & 31;
    int n0 = blockIdx.x * 128, m0 = blockIdx.y * 128;
    if (tid < 128) {
        int m = m0 + tid;
        int lab = labels[(m & 63) * T + (m >> 6)];
        rowlab[tid] = lab < 0 ? 0 : (lab >= V ? V - 1 : lab);
    }
    __syncthreads();
    auto issue = [&](int c, int stage) {
        uint32_t sbase = sb + stage * LG_STAGE_BYTES;
#pragma unroll
        for (int i = 0; i < 16; i++) {
            int slot = i * 256 + tid;
            int comp = slot >> 10, w = slot & 1023;
            int r = w >> 3, ch = w & 7;
            const __half* src;
            if (comp == 0)      src = g_embh + (size_t)rowlab[r] * D;
            else if (comp == 1) src = g_embl + (size_t)rowlab[r] * D;
            else if (comp == 2) src = g_wih_h + (size_t)(n0 + r) * D;
            else                src = g_wih_l + (size_t)(n0 + r) * D;
            src += c * LG_KC + ch * 8;
            uint32_t dst = sbase + comp * LG_COMP_BYTES + sw128(r * 128 + ch * 16);
            CP_ASYNC16(dst, src);
        }
        CP_COMMIT();
    };
    float acc[2][8][4] = {};
    mma_tile_128<D / LG_KC>(sb, issue, acc, warp, lane);
    int wm = warp & 3, wn = warp >> 2;
#pragma unroll
    for (int mt = 0; mt < 2; mt++) {
        int mrow = m0 + wm * 32 + mt * 16 + (lane >> 2);
#pragma unroll
        for (int nt = 0; nt < 8; nt++) {
            int n = n0 + wn * 64 + nt * 8 + (lane & 3) * 2;
            float2 bi = *(const float2*)(b_ih + n);
            float2 bh2 = *(const float2*)(b_hh + n);
            float2 o0 = {acc[mt][nt][0] + bi.x + bh2.x, acc[mt][nt][1] + bi.y + bh2.y};
            float2 o1 = {acc[mt][nt][2] + bi.x + bh2.x, acc[mt][nt][3] + bi.y + bh2.y};
            *(float2*)(g_xw + (size_t)mrow * GD + n) = o0;
            *(float2*)(g_xw + (size_t)(mrow + 8) * GD + n) = o1;
        }
    }
}

// ---------------- gates partials via mma: C[b, gatedim] k-split -------------
#define GT_COMP_BYTES (64 * 128)
__global__ __launch_bounds__(256) void k_gates_mma(int t) {
    __shared__ __align__(1024) char sm[4 * GT_COMP_BYTES];
    uint32_t sb = smem_u32(sm);
    int tid = threadIdx.x, warp = tid >> 5, lane = tid & 31;
    int n0 = blockIdx.x * 64;
    int kb = blockIdx.y * 64;
    int wm = warp & 1, wn = warp >> 1;
    const __half* srcs[4] = {g_hh16, g_hl16,
                             g_whh_h + (size_t)n0 * D, g_whh_l + (size_t)n0 * D};
#pragma unroll
    for (int i = 0; i < 8; i++) {
        int slot = i * 256 + tid;
        int comp = slot >> 9, w = slot & 511;
        int r = w >> 3, ch = w & 7;
        const __half* src = srcs[comp] + (size_t)r * D + kb + ch * 8;
        uint32_t dst = sb + comp * GT_COMP_BYTES + sw128(r * 128 + ch * 16);
        CP_ASYNC16(dst, src);
    }
    CP_COMMIT();
    CP_WAIT(0);
    __syncthreads();
    uint32_t Ah_b = sb, Al_b = sb + GT_COMP_BYTES;
    uint32_t Bh_b = sb + 2 * GT_COMP_BYTES, Bl_b = sb + 3 * GT_COMP_BYTES;
    int lrow = lane & 15;
    uint32_t lcol = (uint32_t)((lane >> 4) << 4);
    float acc[2][2][4] = {};
#pragma unroll
    for (int ks = 0; ks < 4; ks++) {
        uint32_t ah[2][4], al[2][4];
#pragma unroll
        for (int mt = 0; mt < 2; mt++) {
            int r = wm * 32 + mt * 16 + lrow;
            uint32_t bo = sw128((uint32_t)(r * 128 + ks * 32) + lcol);
            ldsm_x4(ah[mt], Ah_b + bo);
            ldsm_x4(al[mt], Al_b + bo);
        }
        uint32_t bh[4], bl[4];
        {
            int r = wn * 16 + lrow;
            uint32_t bo = sw128((uint32_t)(r * 128 + ks * 32) + lcol);
            ldsm_x4(bh, Bh_b + bo);
            ldsm_x4(bl, Bl_b + bo);
        }
#pragma unroll
        for (int mt = 0; mt < 2; mt++)
#pragma unroll
            for (int q = 0; q < 2; q++) {
                mma16816(acc[mt][q], ah[mt], bh[q], bh[q + 2]);
                mma16816(acc[mt][q], ah[mt], bl[q], bl[q + 2]);
                mma16816(acc[mt][q], al[mt], bh[q], bh[q + 2]);
            }
    }
    float* base = g_gpart + (size_t)blockIdx.y * B * GD;
#pragma unroll
    for (int mt = 0; mt < 2; mt++) {
        int br = wm * 32 + mt * 16 + (lane >> 2);
#pragma unroll
        for (int q = 0; q < 2; q++) {
            int n = n0 + wn * 16 + q * 8 + (lane & 3) * 2;
            float2 o0 = {acc[mt][q][0], acc[mt][q][1]};
            float2 o1 = {acc[mt][q][2], acc[mt][q][3]};
            *(float2*)(base + (size_t)br * GD + n) = o0;
            *(float2*)(base + (size_t)(br + 8) * GD + n) = o1;
        }
    }
}

// ======= fused step: cell + scores + softmax + ctx (grid B, 1024 thr) =======
__global__ __launch_bounds__(1024) void k_step(int t, const float* __restrict__ feats) {
    __shared__ __align__(16) float hs[D];
    __shared__ float w[S];
    __shared__ float red[256];
    __shared__ float csum[D];
    int b = blockIdx.x, tid = threadIdx.x;

    // Phase 1: LSTM cell (threads < 512)
    if (tid < D) {
        int d = tid;
        int idx = b * D + d;
        const float* xwrow = g_xw + ((size_t)t * B + b) * GD;
        float ig = xwrow[d], fg = xwrow[D + d], gg = xwrow[2 * D + d], og = xwrow[3 * D + d];
#pragma unroll
        for (int ks = 0; ks < 8; ks++) {
            const float* gp = g_gpart + ((size_t)ks * B + b) * GD;
            ig += gp[d];
            fg += gp[D + d];
            gg += gp[2 * D + d];
            og += gp[3 * D + d];
        }
        float cn = sigf(fg) * g_c[idx] + sigf(ig) * tanhf(gg);
        g_c[idx] = cn;
        float hv = sigf(og) * tanhf(cn);
        hs[d] = hv;
        __half hh = __float2half_rn(hv);
        __half hl = __float2half_rn(hv - __half2float(hh));
        g_hh16[idx] = hh;
        g_hl16[idx] = hl;
        size_t mrow = (size_t)t * B + b;
        g_hcinh[mrow * 2 * D + d] = hh;
        g_hcinl[mrow * 2 * D + d] = hl;
    }
    __syncthreads();

    // Phase 2: scores — 32 warps x 8 s, lane-coalesced over d
    int warp = tid >> 5, lane = tid & 31;
    const float4* h4 = (const float4*)hs;
#pragma unroll
    for (int i = 0; i < 8; i++) {
        int s = warp * 8 + i;
        const float4* f4 = (const float4*)(feats + ((size_t)s * B + b) * D);
        float acc = 0.f;
#pragma unroll
        for (int j = 0; j < 4; j++) {
            int ii = j * 32 + lane;
            float4 f = f4[ii], h = h4[ii];
            acc = fmaf(f.x, h.x, fmaf(f.y, h.y, fmaf(f.z, h.z, fmaf(f.w, h.w, acc))));
        }
#pragma unroll
        for (int o = 16; o; o >>= 1) acc += __shfl_xor_sync(0xffffffffu, acc, o);
        if (lane == 0) w[s] = acc;
    }
    __syncthreads();

    // Phase 3: softmax over S
    float sv = (tid < S) ? w[tid] : -1e30f;
    if (tid < 256) red[tid] = sv;
    __syncthreads();
    for (int st = 128; st; st >>= 1) {
        if (tid < st) red[tid] = fmaxf(red[tid], red[tid + st]);
        __syncthreads();
    }
    float mx = red[0];
    __syncthreads();
    float e = 0.f;
    if (tid < S) {
        e = expf(sv - mx);
        red[tid] = e;
    }
    __syncthreads();
    for (int st = 128; st; st >>= 1) {
        if (tid < st) red[tid] += red[tid + st];
        __syncthreads();
    }
    if (tid < S) w[tid] = e / red[0];
    __syncthreads();

    // Phase 4: ctx — 512 d x 2 s-shards
    int d = tid & 511, sh = tid >> 9;
    const float* fp = feats + ((size_t)(sh * 128) * B + b) * D + d;
    float acc = 0.f;
#pragma unroll 8
    for (int s2 = 0; s2 < 128; s2++)
        acc = fmaf(w[sh * 128 + s2], fp[(size_t)s2 * B * D], acc);
    if (sh == 1) csum[d] = acc;
    __syncthreads();
    if (sh == 0) {
        float cv = acc + csum[d];
        __half ch = __float2half_rn(cv);
        size_t mrow = (size_t)t * B + b;
        g_hcinh[mrow * 2 * D + D + d] = ch;
        g_hcinl[mrow * 2 * D + D + d] = __float2half_rn(cv - __half2float(ch));
    }
}

// ---------------- hcall = [h, ctx] @ W_hc^T + b_hc (mma) --------------------
__global__ __launch_bounds__(256) void k_hc_mma(const float* __restrict__ b_hc) {
    extern __shared__ char smraw[];
    uint32_t sb = (smem_u32(smraw) + 1023u) & ~1023u;
    int tid = threadIdx.x, warp = tid >> 5, lane = tid & 31;
    int n0 = blockIdx.x * 128, m0 = blockIdx.y * 128;
    auto issue = [&](int c, int stage) {
        uint32_t sbase = sb + stage * LG_STAGE_BYTES;
#pragma unroll
        for (int i = 0; i < 16; i++) {
            int slot = i * 256 + tid;
            int comp = slot >> 10, w = slot & 1023;
            int r = w >> 3, ch = w & 7;
            const __half* src;
            if (comp == 0)      src = g_hcinh + (size_t)(m0 + r) * 2 * D;
            else if (comp == 1) src = g_hcinl + (size_t)(m0 + r) * 2 * D;
            else if (comp == 2) src = g_whc_h + (size_t)(n0 + r) * 2 * D;
            else                src = g_whc_l + (size_t)(n0 + r) * 2 * D;
            src += c * LG_KC + ch * 8;
            uint32_t dst = sbase + comp * LG_COMP_BYTES + sw128(r * 128 + ch * 16);
            CP_ASYNC16(dst, src);
        }
        CP_COMMIT();
    };
    float acc[2][8][4] = {};
    mma_tile_128<2 * D / LG_KC>(sb, issue, acc, warp, lane);
    int wm = warp & 3, wn = warp >> 2;
#pragma unroll
    for (int mt = 0; mt < 2; mt++) {
        int mrow = m0 + wm * 32 + mt * 16 + (lane >> 2);
#pragma unroll
        for (int nt = 0; nt < 8; nt++) {
            int n = n0 + wn * 64 + nt * 8 + (lane & 3) * 2;
            float2 bv = *(const float2*)(b_hc + n);
            float2 o0 = {acc[mt][nt][0] + bv.x, acc[mt][nt][1] + bv.y};
            float2 o1 = {acc[mt][nt][2] + bv.x, acc[mt][nt][3] + bv.y};
            *(float2*)(g_hcall + (size_t)mrow * D + n) = o0;
            *(float2*)(g_hcall + (size_t)(mrow + 8) * D + n) = o1;
        }
    }
}

// ---------------- LayerNorm + tanh -> pe (fp16 hi/lo, fused) ---------------
__global__ __launch_bounds__(128) void k_ln_all(const float* __restrict__ ln_g,
                                                const float* __restrict__ ln_b) {
    int m = blockIdx.x;
    int tid = threadIdx.x;
    __shared__ float wsum[4];
    float4 x = *(const float4*)(g_hcall + (size_t)m * D + tid * 4);
    float s = x.x + x.y + x.z + x.w;
#pragma unroll
    for (int o = 16; o; o >>= 1) s += __shfl_xor_sync(0xffffffff, s, o);
    if ((tid & 31) == 0) wsum[tid >> 5] = s;
    __syncthreads();
    float mean = (wsum[0] + wsum[1] + wsum[2] + wsum[3]) * (1.f / D);
    float4 dv = {x.x - mean, x.y - mean, x.z - mean, x.w - mean};
    float v = dv.x * dv.x + dv.y * dv.y + dv.z * dv.z + dv.w * dv.w;
#pragma unroll
    for (int o = 16; o; o >>= 1) v += __shfl_xor_sync(0xffffffff, v, o);
    __syncthreads();
    if ((tid & 31) == 0) wsum[tid >> 5] = v;
    __syncthreads();
    float var = (wsum[0] + wsum[1] + wsum[2] + wsum[3]) * (1.f / D);
    float rs = rsqrtf(var + 1e-5f);
    float4 gl = *(const float4*)(ln_g + tid * 4);
    float4 bl = *(const float4*)(ln_b + tid * 4);
    float y0 = tanhf(fmaf(gl.x, dv.x * rs, bl.x));
    float y1 = tanhf(fmaf(gl.y, dv.y * rs, bl.y));
    float y2 = tanhf(fmaf(gl.z, dv.z * rs, bl.z));
    float y3 = tanhf(fmaf(gl.w, dv.w * rs, bl.w));
    __half h0 = __float2half_rn(y0), h1 = __float2half_rn(y1);
    __half h2 = __float2half_rn(y2), h3 = __float2half_rn(y3);
    size_t o = (size_t)m * D + tid * 4;
    *(__half2*)&g_peh[o] = {h0, h1};
    *(__half2*)&g_peh[o + 2] = {h2, h3};
    *(__half2*)&g_pel[o] = {__float2half_rn(y0 - __half2float(h0)),
                            __float2half_rn(y1 - __half2float(h1))};
    *(__half2*)&g_pel[o + 2] = {__float2half_rn(y2 - __half2float(h2)),
                                __float2half_rn(y3 - __half2float(h3))};
}

// ============ logits via mma.sync fp16 hi/lo split ==========================
// grid (m-tiles, n-tiles): co-resident CTAs share emb tiles -> emb DRAM once.
__global__ __launch_bounds__(256) void k_logits_mma(const float* __restrict__ vbias,
                                                    float* __restrict__ out) {
    extern __shared__ char smraw[];
    uint32_t sb = (smem_u32(smraw) + 1023u) & ~1023u;
    int tid = threadIdx.x, warp = tid >> 5, lane = tid & 31;
    int m0 = blockIdx.x * 128, n0 = blockIdx.y * 128;
    const __half* srcs[4] = {g_peh + (size_t)m0 * D, g_pel + (size_t)m0 * D,
                             g_embh + (size_t)n0 * D, g_embl + (size_t)n0 * D};
    auto issue = [&](int c, int stage) {
        uint32_t sbase = sb + stage * LG_STAGE_BYTES;
#pragma unroll
        for (int i = 0; i < 16; i++) {
            int slot = i * 256 + tid;
            int comp = slot >> 10, w = slot & 1023;
            int r = w >> 3, ch = w & 7;
            const __half* src = srcs[comp] + (size_t)r * D + c * LG_KC + ch * 8;
            uint32_t dst = sbase + comp * LG_COMP_BYTES + sw128(r * 128 + ch * 16);
            CP_ASYNC16(dst, src);
        }
        CP_COMMIT();
    };
    float acc[2][8][4] = {};
    mma_tile_128<D / LG_KC>(sb, issue, acc, warp, lane);
    int wm = warp & 3, wn = warp >> 2;
#pragma unroll
    for (int mt = 0; mt < 2; mt++) {
        int mrow = m0 + wm * 32 + mt * 16 + (lane >> 2);
#pragma unroll
        for (int nt = 0; nt < 8; nt++) {
            int n = n0 + wn * 64 + nt * 8 + (lane & 3) * 2;
            float2 bv = *(const float2*)(vbias + n);
            float2 o0 = {acc[mt][nt][0] + bv.x, acc[mt][nt][1] + bv.y};
            float2 o1 = {acc[mt][nt][2] + bv.x, acc[mt][nt][3] + bv.y};
            *(float2*)(out + (size_t)mrow * V + n) = o0;
            *(float2*)(out + (size_t)(mrow + 8) * V + n) = o1;
        }
    }
}

// ---------------- launch ----------------------------------------------------
extern "C" void kernel_launch(void* const* d_in, const int* in_sizes, int n_in,
                              void* d_out, int out_size) {
    const float* feats = (const float*)d_in[0];
    const int* labels = (const int*)d_in[1];
    const float* W_ih = (const float*)d_in[2];
    const float* W_hh = (const float*)d_in[3];
    const float* b_ih = (const float*)d_in[4];
    const float* b_hh = (const float*)d_in[5];
    const float* W_hc = (const float*)d_in[6];
    const float* b_hc = (const float*)d_in[7];
    const float* ln_g = (const float*)d_in[8];
    const float* ln_b = (const float*)d_in[9];
    const float* emb = (const float*)d_in[10];
    const float* vbias = (const float*)d_in[11];
    float* out = (float*)d_out;

    cudaFuncSetAttribute(k_logits_mma, cudaFuncAttributeMaxDynamicSharedMemorySize,
                         LG_SMEM_REQ);
    cudaFuncSetAttribute(k_xw_mma, cudaFuncAttributeMaxDynamicSharedMemorySize,
                         LG_SMEM_REQ);
    cudaFuncSetAttribute(k_hc_mma, cudaFuncAttributeMaxDynamicSharedMemorySize,
                         LG_SMEM_REQ);

    __half *embh, *embl, *whhh, *whhl, *wihh, *wihl, *whch, *whcl;
    cudaGetSymbolAddress((void**)&embh, g_embh);
    cudaGetSymbolAddress((void**)&embl, g_embl);
    cudaGetSymbolAddress((void**)&whhh, g_whh_h);
    cudaGetSymbolAddress((void**)&whhl, g_whh_l);
    cudaGetSymbolAddress((void**)&wihh, g_wih_h);
    cudaGetSymbolAddress((void**)&wihl, g_wih_l);
    cudaGetSymbolAddress((void**)&whch, g_whc_h);
    cudaGetSymbolAddress((void**)&whcl, g_whc_l);

    k_init<<<(B * D) / 256, 256>>>(feats);
    k_cvt<<<(V * D / 4) / 256, 256>>>(emb, embh, embl);
    k_cvt<<<(GD * D / 4) / 256, 256>>>(W_hh, whhh, whhl);
    k_cvt<<<(GD * D / 4) / 256, 256>>>(W_ih, wihh, wihl);
    k_cvt<<<(D * 2 * D / 4) / 256, 256>>>(W_hc, whch, whcl);
    k_xw_mma<<<dim3(GD / 128, (T * B) / 128), 256, LG_SMEM_REQ>>>(labels, b_ih, b_hh);
    for (int t = 0; t < T; t++) {
        k_gates_mma<<<dim3(GD / 64, D / 64), 256>>>(t);
        k_step<<<B, 1024>>>(t, feats);
    }
    k_hc_mma<<<dim3(D / 128, (T * B) / 128), 256, LG_SMEM_REQ>>>(b_hc);
    k_ln_all<<<T * B, 128>>>(ln_g, ln_b);
    k_logits_mma<<<dim3((T * B) / 128, V / 128), 256, LG_SMEM_REQ>>>(vbias, out);
}